// round 1
// baseline (speedup 1.0000x reference)
#include <cuda_runtime.h>
#include <cuda_bf16.h>
#include <math.h>

// Problem constants
#define BWIN 256      // windows*batch
#define NTOK 256      // tokens per window
#define CDIM 384
#define NHEAD 12
#define HDIM 32
#define MROWS (BWIN*NTOK)   // 65536
#define TBL 961             // (2*16-1)^2
#define CPBH 512

// ---------------- scratch (device globals; no allocs allowed) ----------------
__device__ float g_qkv[3ull * MROWS * CDIM];     // [3][M][384]  (~302 MB)
__device__ float g_attout[(size_t)MROWS * CDIM]; // [M][384]     (~100 MB)
__device__ float g_bt[TBL * NHEAD];              // raw cpb bias table
__device__ float g_rpb[(size_t)NHEAD * NTOK * NTOK]; // 16*sigmoid(bt[rpi]) [h][i][j]

// ---------------- QKV GEMM: out[m][c] = sum_k x[m][k]*W[c][k] + bias[c] ------
// M=65536, N=1152, K=384. 128x128 tile, 256 threads, 8x8 micro-tile, K-tile 8.
__global__ __launch_bounds__(256) void qkv_gemm_kernel(
    const float* __restrict__ x, const float* __restrict__ w,
    const float* __restrict__ qb, const float* __restrict__ vb) {
    __shared__ float As[8][128];
    __shared__ float Bs[8][128];
    const int m0 = blockIdx.y * 128;
    const int n0 = blockIdx.x * 128;
    const int t = threadIdx.x;
    const int lr = t >> 1;           // 0..127 row within tile for loads
    const int lc = (t & 1) << 2;     // 0 or 4 (float4 column group)
    const int tx = (t & 15) << 3;    // 0..120 micro-tile col
    const int ty = (t >> 4) << 3;    // 0..120 micro-tile row

    const float* ap = x + (size_t)(m0 + lr) * CDIM + lc;
    const float* bp = w + (size_t)(n0 + lr) * CDIM + lc;

    float acc[8][8];
#pragma unroll
    for (int i = 0; i < 8; i++)
#pragma unroll
        for (int j = 0; j < 8; j++) acc[i][j] = 0.f;

    for (int k0 = 0; k0 < CDIM; k0 += 8) {
        float4 a4 = *(const float4*)(ap + k0);
        float4 b4 = *(const float4*)(bp + k0);
        As[lc + 0][lr] = a4.x; As[lc + 1][lr] = a4.y;
        As[lc + 2][lr] = a4.z; As[lc + 3][lr] = a4.w;
        Bs[lc + 0][lr] = b4.x; Bs[lc + 1][lr] = b4.y;
        Bs[lc + 2][lr] = b4.z; Bs[lc + 3][lr] = b4.w;
        __syncthreads();
#pragma unroll
        for (int kk = 0; kk < 8; kk++) {
            float a[8], b[8];
            *(float4*)(a)     = *(const float4*)(&As[kk][ty]);
            *(float4*)(a + 4) = *(const float4*)(&As[kk][ty + 4]);
            *(float4*)(b)     = *(const float4*)(&Bs[kk][tx]);
            *(float4*)(b + 4) = *(const float4*)(&Bs[kk][tx + 4]);
#pragma unroll
            for (int i = 0; i < 8; i++)
#pragma unroll
                for (int j = 0; j < 8; j++) acc[i][j] += a[i] * b[j];
        }
        __syncthreads();
    }

    // epilogue: tile never crosses the 384 boundary (384 = 3*128)
    const int which = n0 / CDIM;
    const int cbase = (n0 % CDIM) + tx;
    float bias[8];
#pragma unroll
    for (int j = 0; j < 8; j++) {
        int c = cbase + j;
        bias[j] = (which == 0) ? qb[c] : (which == 2 ? vb[c] : 0.f);
    }
    float* outp = g_qkv + (size_t)which * MROWS * CDIM;
#pragma unroll
    for (int i = 0; i < 8; i++) {
        float* orow = outp + (size_t)(m0 + ty + i) * CDIM + cbase;
        float4 o0 = make_float4(acc[i][0] + bias[0], acc[i][1] + bias[1],
                                acc[i][2] + bias[2], acc[i][3] + bias[3]);
        float4 o1 = make_float4(acc[i][4] + bias[4], acc[i][5] + bias[5],
                                acc[i][6] + bias[6], acc[i][7] + bias[7]);
        *(float4*)(orow) = o0;
        *(float4*)(orow + 4) = o1;
    }
}

// ---------------- CPB MLP: bt[r][h] = (relu(table[r]@w1^T + b1)) @ w2^T ------
__global__ __launch_bounds__(128) void cpb_kernel(
    const float* __restrict__ table, const float* __restrict__ w1,
    const float* __restrict__ b1, const float* __restrict__ w2) {
    __shared__ float hid[CPBH];
    __shared__ float part[NHEAD][9];
    const int r = blockIdx.x;
    const float t0 = table[r * 2 + 0];
    const float t1 = table[r * 2 + 1];
    for (int j = threadIdx.x; j < CPBH; j += 128)
        hid[j] = fmaxf(w1[j * 2] * t0 + w1[j * 2 + 1] * t1 + b1[j], 0.f);
    __syncthreads();
    const int t = threadIdx.x;
    if (t < 96) {
        const int h = t >> 3, seg = t & 7;
        float s = 0.f;
        const float* wr = w2 + h * CPBH + seg * 64;
        const float* hr = hid + seg * 64;
#pragma unroll 8
        for (int j = 0; j < 64; j++) s += hr[j] * wr[j];
        part[h][seg] = s;
    }
    __syncthreads();
    if (t < NHEAD) {
        float s = 0.f;
#pragma unroll
        for (int seg = 0; seg < 8; seg++) s += part[t][seg];
        g_bt[r * NHEAD + t] = s;
    }
}

// ---------------- rpb expand: g_rpb[h][i][j] = 16*sigmoid(bt[rpi[i][j]][h]) --
__global__ __launch_bounds__(256) void rpb_kernel(const int* __restrict__ rpi) {
    const int h = blockIdx.x >> 8;
    const int i = blockIdx.x & 255;
    const int j = threadIdx.x;
    const int idx = rpi[i * NTOK + j];
    const float v = g_bt[idx * NHEAD + h];
    g_rpb[((size_t)(h * NTOK + i)) * NTOK + j] = 16.f / (1.f + __expf(-v));
}

// ---------------- fused attention: one CTA per (window, head) ----------------
// 128 threads, each owns 2 query rows (t, t+128). k,v in smem (stride 36 pad).
#define KVS 36
__global__ __launch_bounds__(128) void attn_kernel(const float* __restrict__ lscale) {
    extern __shared__ float sm[];
    float* kn = sm;                 // [256][36] normalized k
    float* vn = sm + NTOK * KVS;    // [256][36] v

    const int blk = blockIdx.x;
    const int b = blk / NHEAD;
    const int h = blk % NHEAD;
    const int t = threadIdx.x;

    const size_t base = ((size_t)b * NTOK) * CDIM + h * HDIM;
    const float* gq = g_qkv + base;
    const float* gk = g_qkv + (size_t)1 * MROWS * CDIM + base;
    const float* gv = g_qkv + (size_t)2 * MROWS * CDIM + base;

    const float scale = __expf(fminf(lscale[h], 4.60517018598809f)); // ln(100)

    // load + normalize k, load v (2 rows per thread)
    for (int r = t; r < NTOK; r += 128) {
        float kv[32];
        const float* kr = gk + (size_t)r * CDIM;
#pragma unroll
        for (int d = 0; d < HDIM; d += 4) *(float4*)(kv + d) = *(const float4*)(kr + d);
        float ss = 0.f;
#pragma unroll
        for (int d = 0; d < HDIM; d++) ss += kv[d] * kv[d];
        const float rn = 1.f / fmaxf(sqrtf(ss), 1e-12f);
#pragma unroll
        for (int d = 0; d < HDIM; d++) kn[r * KVS + d] = kv[d] * rn;
        const float* vr = gv + (size_t)r * CDIM;
#pragma unroll
        for (int d = 0; d < HDIM; d += 4) {
            float4 v4 = *(const float4*)(vr + d);
            vn[r * KVS + d + 0] = v4.x; vn[r * KVS + d + 1] = v4.y;
            vn[r * KVS + d + 2] = v4.z; vn[r * KVS + d + 3] = v4.w;
        }
    }

    // load + normalize q (scale folded in)
    float qn[2][HDIM];
#pragma unroll
    for (int qi = 0; qi < 2; qi++) {
        const int r = t + qi * 128;
        const float* qr = gq + (size_t)r * CDIM;
        float qv[32];
#pragma unroll
        for (int d = 0; d < HDIM; d += 4) *(float4*)(qv + d) = *(const float4*)(qr + d);
        float ss = 0.f;
#pragma unroll
        for (int d = 0; d < HDIM; d++) ss += qv[d] * qv[d];
        const float rn = scale / fmaxf(sqrtf(ss), 1e-12f);
#pragma unroll
        for (int d = 0; d < HDIM; d++) qn[qi][d] = qv[d] * rn;
    }
    __syncthreads();

    const float* rpb0 = g_rpb + ((size_t)h * NTOK) * NTOK;

    float m[2] = {-1e30f, -1e30f};
    float l[2] = {0.f, 0.f};
    float o[2][HDIM];
#pragma unroll
    for (int qi = 0; qi < 2; qi++)
#pragma unroll
        for (int d = 0; d < HDIM; d++) o[qi][d] = 0.f;

    for (int j0 = 0; j0 < NTOK; j0 += 16) {
        float s[2][16];
        // scores: broadcast smem reads, 2 FMAs per LDS lane
#pragma unroll
        for (int jj = 0; jj < 16; jj++) {
            const float* kr = kn + (j0 + jj) * KVS;
            float d0 = 0.f, d1 = 0.f;
#pragma unroll
            for (int d = 0; d < HDIM; d += 4) {
                float4 k4 = *(const float4*)(kr + d);
                d0 += qn[0][d] * k4.x; d0 += qn[0][d + 1] * k4.y;
                d0 += qn[0][d + 2] * k4.z; d0 += qn[0][d + 3] * k4.w;
                d1 += qn[1][d] * k4.x; d1 += qn[1][d + 1] * k4.y;
                d1 += qn[1][d + 2] * k4.z; d1 += qn[1][d + 3] * k4.w;
            }
            s[0][jj] = d0; s[1][jj] = d1;
        }
        // + relative position bias
#pragma unroll
        for (int qi = 0; qi < 2; qi++) {
            const float* rp = rpb0 + (size_t)(t + qi * 128) * NTOK + j0;
#pragma unroll
            for (int jj = 0; jj < 16; jj += 4) {
                float4 r4 = *(const float4*)(rp + jj);
                s[qi][jj + 0] += r4.x; s[qi][jj + 1] += r4.y;
                s[qi][jj + 2] += r4.z; s[qi][jj + 3] += r4.w;
            }
        }
        // online softmax update (p stored back into s)
#pragma unroll
        for (int qi = 0; qi < 2; qi++) {
            float cmax = s[qi][0];
#pragma unroll
            for (int jj = 1; jj < 16; jj++) cmax = fmaxf(cmax, s[qi][jj]);
            const float mn = fmaxf(m[qi], cmax);
            const float al = __expf(m[qi] - mn);
            m[qi] = mn;
            l[qi] *= al;
#pragma unroll
            for (int d = 0; d < HDIM; d++) o[qi][d] *= al;
            float ls = 0.f;
#pragma unroll
            for (int jj = 0; jj < 16; jj++) {
                const float p = __expf(s[qi][jj] - mn);
                s[qi][jj] = p;
                ls += p;
            }
            l[qi] += ls;
        }
        // P @ V: broadcast v rows, 2 FMAs per LDS lane
#pragma unroll
        for (int jj = 0; jj < 16; jj++) {
            const float p0 = s[0][jj], p1 = s[1][jj];
            const float* vr = vn + (j0 + jj) * KVS;
#pragma unroll
            for (int d = 0; d < HDIM; d += 4) {
                float4 v4 = *(const float4*)(vr + d);
                o[0][d + 0] += p0 * v4.x; o[0][d + 1] += p0 * v4.y;
                o[0][d + 2] += p0 * v4.z; o[0][d + 3] += p0 * v4.w;
                o[1][d + 0] += p1 * v4.x; o[1][d + 1] += p1 * v4.y;
                o[1][d + 2] += p1 * v4.z; o[1][d + 3] += p1 * v4.w;
            }
        }
    }

    // finalize -> g_attout[b*256+n][h*32+d]
#pragma unroll
    for (int qi = 0; qi < 2; qi++) {
        const float inv = 1.f / l[qi];
        const int r = t + qi * 128;
        float* op = g_attout + ((size_t)(b * NTOK + r)) * CDIM + h * HDIM;
#pragma unroll
        for (int d = 0; d < HDIM; d += 4) {
            float4 ov = make_float4(o[qi][d] * inv, o[qi][d + 1] * inv,
                                    o[qi][d + 2] * inv, o[qi][d + 3] * inv);
            *(float4*)(op + d) = ov;
        }
    }
}

// ---------------- proj GEMM: out[m][c] = attout[m][:] . proj_w[c][:] + pb[c] -
__global__ __launch_bounds__(256) void proj_gemm_kernel(
    const float* __restrict__ w, const float* __restrict__ pb,
    float* __restrict__ out) {
    __shared__ float As[8][128];
    __shared__ float Bs[8][128];
    const int m0 = blockIdx.y * 128;
    const int n0 = blockIdx.x * 128;
    const int t = threadIdx.x;
    const int lr = t >> 1;
    const int lc = (t & 1) << 2;
    const int tx = (t & 15) << 3;
    const int ty = (t >> 4) << 3;

    const float* ap = g_attout + (size_t)(m0 + lr) * CDIM + lc;
    const float* bp = w + (size_t)(n0 + lr) * CDIM + lc;

    float acc[8][8];
#pragma unroll
    for (int i = 0; i < 8; i++)
#pragma unroll
        for (int j = 0; j < 8; j++) acc[i][j] = 0.f;

    for (int k0 = 0; k0 < CDIM; k0 += 8) {
        float4 a4 = *(const float4*)(ap + k0);
        float4 b4 = *(const float4*)(bp + k0);
        As[lc + 0][lr] = a4.x; As[lc + 1][lr] = a4.y;
        As[lc + 2][lr] = a4.z; As[lc + 3][lr] = a4.w;
        Bs[lc + 0][lr] = b4.x; Bs[lc + 1][lr] = b4.y;
        Bs[lc + 2][lr] = b4.z; Bs[lc + 3][lr] = b4.w;
        __syncthreads();
#pragma unroll
        for (int kk = 0; kk < 8; kk++) {
            float a[8], b[8];
            *(float4*)(a)     = *(const float4*)(&As[kk][ty]);
            *(float4*)(a + 4) = *(const float4*)(&As[kk][ty + 4]);
            *(float4*)(b)     = *(const float4*)(&Bs[kk][tx]);
            *(float4*)(b + 4) = *(const float4*)(&Bs[kk][tx + 4]);
#pragma unroll
            for (int i = 0; i < 8; i++)
#pragma unroll
                for (int j = 0; j < 8; j++) acc[i][j] += a[i] * b[j];
        }
        __syncthreads();
    }

    const int cbase = n0 + tx;
    float bias[8];
#pragma unroll
    for (int j = 0; j < 8; j++) bias[j] = pb[cbase + j];
#pragma unroll
    for (int i = 0; i < 8; i++) {
        float* orow = out + (size_t)(m0 + ty + i) * CDIM + cbase;
        float4 o0 = make_float4(acc[i][0] + bias[0], acc[i][1] + bias[1],
                                acc[i][2] + bias[2], acc[i][3] + bias[3]);
        float4 o1 = make_float4(acc[i][4] + bias[4], acc[i][5] + bias[5],
                                acc[i][6] + bias[6], acc[i][7] + bias[7]);
        *(float4*)(orow) = o0;
        *(float4*)(orow + 4) = o1;
    }
}

// ---------------- launch ----------------
extern "C" void kernel_launch(void* const* d_in, const int* in_sizes, int n_in,
                              void* d_out, int out_size) {
    const float* x      = (const float*)d_in[0];
    const float* qkv_w  = (const float*)d_in[1];
    const float* q_bias = (const float*)d_in[2];
    const float* v_bias = (const float*)d_in[3];
    const float* lscale = (const float*)d_in[4];
    const float* cpb_w1 = (const float*)d_in[5];
    const float* cpb_b1 = (const float*)d_in[6];
    const float* cpb_w2 = (const float*)d_in[7];
    const float* proj_w = (const float*)d_in[8];
    const float* proj_b = (const float*)d_in[9];
    const float* table  = (const float*)d_in[10];
    const int*   rpi    = (const int*)d_in[11];
    float* out = (float*)d_out;

    static int smem_set = 0;
    // idempotent; safe to call every time (not a stream op, no allocation)
    cudaFuncSetAttribute(attn_kernel, cudaFuncAttributeMaxDynamicSharedMemorySize,
                         2 * NTOK * KVS * (int)sizeof(float));
    (void)smem_set;

    qkv_gemm_kernel<<<dim3(9, 512), 256>>>(x, qkv_w, q_bias, v_bias);
    cpb_kernel<<<TBL, 128>>>(table, cpb_w1, cpb_b1, cpb_w2);
    rpb_kernel<<<NHEAD * NTOK, 256>>>(rpi);
    attn_kernel<<<BWIN * NHEAD, 128, 2 * NTOK * KVS * (int)sizeof(float)>>>(lscale);
    proj_gemm_kernel<<<dim3(3, 512), 256>>>(proj_w, proj_b, out);
    (void)in_sizes; (void)n_in; (void)out_size;
}

// round 3
// speedup vs baseline: 1.9057x; 1.9057x over previous
#include <cuda_runtime.h>
#include <cuda_bf16.h>
#include <math.h>
#include <stdint.h>

// Problem constants
#define BWIN 256      // windows*batch
#define NTOK 256      // tokens per window
#define CDIM 384
#define NHEAD 12
#define HDIM 32
#define MROWS (BWIN*NTOK)   // 65536
#define TBL 961             // (2*16-1)^2
#define CPBH 512

// ---------------- scratch (device globals; no allocs allowed) ----------------
__device__ float g_qkv[3ull * MROWS * CDIM];     // [3][M][384]
__device__ float g_attout[(size_t)MROWS * CDIM]; // [M][384]
__device__ float g_bt[TBL * NHEAD];              // raw cpb bias table
__device__ float g_rpb[(size_t)NHEAD * NTOK * NTOK]; // 16*sigmoid(bt[rpi]) [h][i][j]

// ==================== tf32 tensor-core GEMM ====================
// C[m][n] = sum_k A[m][k] * B[n][k]  (both K-contiguous, K=384)
// CTA tile 128x128, 256 threads = 8 warps in 2(m) x 4(n), warp tile m64 x n32.
// mma.sync.aligned.m16n8k8.tf32 ; K-chunk 16, double-buffered smem.

#define ASTR 20   // smem row stride (16 + 4 pad) -> conflict-free frag LDS

__device__ __forceinline__ uint32_t f2tf(float f) {
    uint32_t u;
    asm("cvt.rna.tf32.f32 %0, %1;" : "=r"(u) : "f"(f));
    return u;
}

__device__ __forceinline__ void mma_tf32(float* c, const uint32_t* a, const uint32_t* b) {
    asm volatile(
        "mma.sync.aligned.m16n8k8.row.col.f32.tf32.tf32.f32 "
        "{%0,%1,%2,%3}, {%4,%5,%6,%7}, {%8,%9}, {%0,%1,%2,%3};\n"
        : "+f"(c[0]), "+f"(c[1]), "+f"(c[2]), "+f"(c[3])
        : "r"(a[0]), "r"(a[1]), "r"(a[2]), "r"(a[3]), "r"(b[0]), "r"(b[1]));
}

// Core mainloop: Ag/Bg point at the CTA's first row of A/B (K-contiguous, ld=384).
// NCHUNK = 384/16 = 24.
__device__ __forceinline__ void mma_gemm_core(
    const float* __restrict__ Ag, const float* __restrict__ Bg,
    float acc[4][4][4]) {
    __shared__ uint32_t As[2][128 * ASTR];
    __shared__ uint32_t Bs[2][128 * ASTR];

    const int tid = threadIdx.x;
    const int lane = tid & 31;
    const int wm = ((tid >> 5) >> 2) * 64;   // warp m offset (0,64)
    const int wn = ((tid >> 5) & 3) * 32;    // warp n offset (0..96)
    const int lr = tid >> 2;                 // 0..63 load row
    const int lq = (tid & 3) * 4;            // 0,4,8,12 load col (float4)

    const int g = lane >> 2;   // 0..7
    const int tg = lane & 3;   // 0..3

    float4 pa0, pa1, pb0, pb1;
    // prologue: chunk 0
    pa0 = *(const float4*)(Ag + (size_t)lr * CDIM + lq);
    pa1 = *(const float4*)(Ag + (size_t)(lr + 64) * CDIM + lq);
    pb0 = *(const float4*)(Bg + (size_t)lr * CDIM + lq);
    pb1 = *(const float4*)(Bg + (size_t)(lr + 64) * CDIM + lq);
    {
        uint4 u;
        u.x = f2tf(pa0.x); u.y = f2tf(pa0.y); u.z = f2tf(pa0.z); u.w = f2tf(pa0.w);
        *(uint4*)&As[0][lr * ASTR + lq] = u;
        u.x = f2tf(pa1.x); u.y = f2tf(pa1.y); u.z = f2tf(pa1.z); u.w = f2tf(pa1.w);
        *(uint4*)&As[0][(lr + 64) * ASTR + lq] = u;
        u.x = f2tf(pb0.x); u.y = f2tf(pb0.y); u.z = f2tf(pb0.z); u.w = f2tf(pb0.w);
        *(uint4*)&Bs[0][lr * ASTR + lq] = u;
        u.x = f2tf(pb1.x); u.y = f2tf(pb1.y); u.z = f2tf(pb1.z); u.w = f2tf(pb1.w);
        *(uint4*)&Bs[0][(lr + 64) * ASTR + lq] = u;
    }
    __syncthreads();

    int cur = 0;
    const int NCHUNK = CDIM / 16;
#pragma unroll 1
    for (int c = 0; c < NCHUNK; c++) {
        if (c + 1 < NCHUNK) {
            const int k0 = (c + 1) * 16;
            pa0 = *(const float4*)(Ag + (size_t)lr * CDIM + k0 + lq);
            pa1 = *(const float4*)(Ag + (size_t)(lr + 64) * CDIM + k0 + lq);
            pb0 = *(const float4*)(Bg + (size_t)lr * CDIM + k0 + lq);
            pb1 = *(const float4*)(Bg + (size_t)(lr + 64) * CDIM + k0 + lq);
        }
        // compute: 2 k-steps of 8
#pragma unroll
        for (int ks = 0; ks < 2; ks++) {
            const int kk = ks * 8 + tg;
            uint32_t a[4][4], b[4][2];
#pragma unroll
            for (int mt = 0; mt < 4; mt++) {
                const int row = wm + mt * 16 + g;
                a[mt][0] = As[cur][row * ASTR + kk];
                a[mt][1] = As[cur][(row + 8) * ASTR + kk];
                a[mt][2] = As[cur][row * ASTR + kk + 4];
                a[mt][3] = As[cur][(row + 8) * ASTR + kk + 4];
            }
#pragma unroll
            for (int nt = 0; nt < 4; nt++) {
                const int col = wn + nt * 8 + g;
                b[nt][0] = Bs[cur][col * ASTR + kk];
                b[nt][1] = Bs[cur][col * ASTR + kk + 4];
            }
#pragma unroll
            for (int mt = 0; mt < 4; mt++)
#pragma unroll
                for (int nt = 0; nt < 4; nt++)
                    mma_tf32(acc[mt][nt], a[mt], b[nt]);
        }
        if (c + 1 < NCHUNK) {
            const int nb = cur ^ 1;
            uint4 u;
            u.x = f2tf(pa0.x); u.y = f2tf(pa0.y); u.z = f2tf(pa0.z); u.w = f2tf(pa0.w);
            *(uint4*)&As[nb][lr * ASTR + lq] = u;
            u.x = f2tf(pa1.x); u.y = f2tf(pa1.y); u.z = f2tf(pa1.z); u.w = f2tf(pa1.w);
            *(uint4*)&As[nb][(lr + 64) * ASTR + lq] = u;
            u.x = f2tf(pb0.x); u.y = f2tf(pb0.y); u.z = f2tf(pb0.z); u.w = f2tf(pb0.w);
            *(uint4*)&Bs[nb][lr * ASTR + lq] = u;
            u.x = f2tf(pb1.x); u.y = f2tf(pb1.y); u.z = f2tf(pb1.z); u.w = f2tf(pb1.w);
            *(uint4*)&Bs[nb][(lr + 64) * ASTR + lq] = u;
        }
        __syncthreads();
        cur ^= 1;
    }
}

// QKV: A = x [65536,384], B = qkv_w [1152,384]; out -> g_qkv[3][M][384] + bias
__global__ __launch_bounds__(256) void qkv_mma_kernel(
    const float* __restrict__ x, const float* __restrict__ w,
    const float* __restrict__ qb, const float* __restrict__ vb) {
    float acc[4][4][4];
#pragma unroll
    for (int i = 0; i < 4; i++)
#pragma unroll
        for (int j = 0; j < 4; j++)
#pragma unroll
            for (int k = 0; k < 4; k++) acc[i][j][k] = 0.f;

    const float* Ag = x + (size_t)blockIdx.y * 128 * CDIM;
    const float* Bg = w + (size_t)blockIdx.x * 128 * CDIM;
    mma_gemm_core(Ag, Bg, acc);

    const int tid = threadIdx.x;
    const int lane = tid & 31;
    const int wm = ((tid >> 5) >> 2) * 64;
    const int wn = ((tid >> 5) & 3) * 32;
    const int g = lane >> 2, tg = lane & 3;

    const int nbase = blockIdx.x * 128;
    const int which = nbase / CDIM;           // 0=q, 1=k, 2=v
    const int cb = nbase % CDIM;
    float* outp = g_qkv + (size_t)which * MROWS * CDIM;

#pragma unroll
    for (int mt = 0; mt < 4; mt++) {
        const int row = blockIdx.y * 128 + wm + mt * 16 + g;
#pragma unroll
        for (int nt = 0; nt < 4; nt++) {
            const int col = cb + wn + nt * 8 + 2 * tg;
            float b0 = 0.f, b1 = 0.f;
            if (which == 0) { b0 = qb[col]; b1 = qb[col + 1]; }
            else if (which == 2) { b0 = vb[col]; b1 = vb[col + 1]; }
            float2 o0 = make_float2(acc[mt][nt][0] + b0, acc[mt][nt][1] + b1);
            float2 o1 = make_float2(acc[mt][nt][2] + b0, acc[mt][nt][3] + b1);
            *(float2*)(outp + (size_t)row * CDIM + col) = o0;
            *(float2*)(outp + (size_t)(row + 8) * CDIM + col) = o1;
        }
    }
}

// Proj: A = g_attout [65536,384], B = proj_w [384,384]; out -> d_out + bias
__global__ __launch_bounds__(256) void proj_mma_kernel(
    const float* __restrict__ w, const float* __restrict__ pb,
    float* __restrict__ out) {
    float acc[4][4][4];
#pragma unroll
    for (int i = 0; i < 4; i++)
#pragma unroll
        for (int j = 0; j < 4; j++)
#pragma unroll
            for (int k = 0; k < 4; k++) acc[i][j][k] = 0.f;

    const float* Ag = g_attout + (size_t)blockIdx.y * 128 * CDIM;
    const float* Bg = w + (size_t)blockIdx.x * 128 * CDIM;
    mma_gemm_core(Ag, Bg, acc);

    const int tid = threadIdx.x;
    const int lane = tid & 31;
    const int wm = ((tid >> 5) >> 2) * 64;
    const int wn = ((tid >> 5) & 3) * 32;
    const int g = lane >> 2, tg = lane & 3;
    const int nbase = blockIdx.x * 128;

#pragma unroll
    for (int mt = 0; mt < 4; mt++) {
        const int row = blockIdx.y * 128 + wm + mt * 16 + g;
#pragma unroll
        for (int nt = 0; nt < 4; nt++) {
            const int col = nbase + wn + nt * 8 + 2 * tg;
            const float b0 = pb[col], b1 = pb[col + 1];
            float2 o0 = make_float2(acc[mt][nt][0] + b0, acc[mt][nt][1] + b1);
            float2 o1 = make_float2(acc[mt][nt][2] + b0, acc[mt][nt][3] + b1);
            *(float2*)(out + (size_t)row * CDIM + col) = o0;
            *(float2*)(out + (size_t)(row + 8) * CDIM + col) = o1;
        }
    }
}

// ---------------- CPB MLP: bt[r][h] = (relu(table[r]@w1^T + b1)) @ w2^T ------
__global__ __launch_bounds__(128) void cpb_kernel(
    const float* __restrict__ table, const float* __restrict__ w1,
    const float* __restrict__ b1, const float* __restrict__ w2) {
    __shared__ float hid[CPBH];
    __shared__ float part[NHEAD][9];
    const int r = blockIdx.x;
    const float t0 = table[r * 2 + 0];
    const float t1 = table[r * 2 + 1];
    for (int j = threadIdx.x; j < CPBH; j += 128)
        hid[j] = fmaxf(w1[j * 2] * t0 + w1[j * 2 + 1] * t1 + b1[j], 0.f);
    __syncthreads();
    const int t = threadIdx.x;
    if (t < 96) {
        const int h = t >> 3, seg = t & 7;
        float s = 0.f;
        const float* wr = w2 + h * CPBH + seg * 64;
        const float* hr = hid + seg * 64;
#pragma unroll 8
        for (int j = 0; j < 64; j++) s += hr[j] * wr[j];
        part[h][seg] = s;
    }
    __syncthreads();
    if (t < NHEAD) {
        float s = 0.f;
#pragma unroll
        for (int seg = 0; seg < 8; seg++) s += part[t][seg];
        g_bt[r * NHEAD + t] = s;
    }
}

// ---------------- rpb expand: g_rpb[h][i][j] = 16*sigmoid(bt[rpi[i][j]][h]) --
__global__ __launch_bounds__(256) void rpb_kernel(const int* __restrict__ rpi) {
    const int h = blockIdx.x >> 8;
    const int i = blockIdx.x & 255;
    const int j = threadIdx.x;
    const int idx = rpi[i * NTOK + j];
    const float v = g_bt[idx * NHEAD + h];
    g_rpb[((size_t)(h * NTOK + i)) * NTOK + j] = 16.f / (1.f + __expf(-v));
}

// ---------------- fused attention: one CTA per (window, head) ----------------
#define KVS 36
__global__ __launch_bounds__(128) void attn_kernel(const float* __restrict__ lscale) {
    extern __shared__ float sm[];
    float* kn = sm;                 // [256][36] normalized k
    float* vn = sm + NTOK * KVS;    // [256][36] v

    const int blk = blockIdx.x;
    const int b = blk / NHEAD;
    const int h = blk % NHEAD;
    const int t = threadIdx.x;

    const size_t base = ((size_t)b * NTOK) * CDIM + h * HDIM;
    const float* gq = g_qkv + base;
    const float* gk = g_qkv + (size_t)1 * MROWS * CDIM + base;
    const float* gv = g_qkv + (size_t)2 * MROWS * CDIM + base;

    const float scale = __expf(fminf(lscale[h], 4.60517018598809f)); // ln(100)

    for (int r = t; r < NTOK; r += 128) {
        float kv[32];
        const float* kr = gk + (size_t)r * CDIM;
#pragma unroll
        for (int d = 0; d < HDIM; d += 4) *(float4*)(kv + d) = *(const float4*)(kr + d);
        float ss = 0.f;
#pragma unroll
        for (int d = 0; d < HDIM; d++) ss += kv[d] * kv[d];
        const float rn = 1.f / fmaxf(sqrtf(ss), 1e-12f);
#pragma unroll
        for (int d = 0; d < HDIM; d++) kn[r * KVS + d] = kv[d] * rn;
        const float* vr = gv + (size_t)r * CDIM;
#pragma unroll
        for (int d = 0; d < HDIM; d += 4) {
            float4 v4 = *(const float4*)(vr + d);
            vn[r * KVS + d + 0] = v4.x; vn[r * KVS + d + 1] = v4.y;
            vn[r * KVS + d + 2] = v4.z; vn[r * KVS + d + 3] = v4.w;
        }
    }

    float qn[2][HDIM];
#pragma unroll
    for (int qi = 0; qi < 2; qi++) {
        const int r = t + qi * 128;
        const float* qr = gq + (size_t)r * CDIM;
        float qv[32];
#pragma unroll
        for (int d = 0; d < HDIM; d += 4) *(float4*)(qv + d) = *(const float4*)(qr + d);
        float ss = 0.f;
#pragma unroll
        for (int d = 0; d < HDIM; d++) ss += qv[d] * qv[d];
        const float rn = scale / fmaxf(sqrtf(ss), 1e-12f);
#pragma unroll
        for (int d = 0; d < HDIM; d++) qn[qi][d] = qv[d] * rn;
    }
    __syncthreads();

    const float* rpb0 = g_rpb + ((size_t)h * NTOK) * NTOK;

    float m[2] = {-1e30f, -1e30f};
    float l[2] = {0.f, 0.f};
    float o[2][HDIM];
#pragma unroll
    for (int qi = 0; qi < 2; qi++)
#pragma unroll
        for (int d = 0; d < HDIM; d++) o[qi][d] = 0.f;

    for (int j0 = 0; j0 < NTOK; j0 += 16) {
        float s[2][16];
#pragma unroll
        for (int jj = 0; jj < 16; jj++) {
            const float* kr = kn + (j0 + jj) * KVS;
            float d0 = 0.f, d1 = 0.f;
#pragma unroll
            for (int d = 0; d < HDIM; d += 4) {
                float4 k4 = *(const float4*)(kr + d);
                d0 += qn[0][d] * k4.x; d0 += qn[0][d + 1] * k4.y;
                d0 += qn[0][d + 2] * k4.z; d0 += qn[0][d + 3] * k4.w;
                d1 += qn[1][d] * k4.x; d1 += qn[1][d + 1] * k4.y;
                d1 += qn[1][d + 2] * k4.z; d1 += qn[1][d + 3] * k4.w;
            }
            s[0][jj] = d0; s[1][jj] = d1;
        }
#pragma unroll
        for (int qi = 0; qi < 2; qi++) {
            const float* rp = rpb0 + (size_t)(t + qi * 128) * NTOK + j0;
#pragma unroll
            for (int jj = 0; jj < 16; jj += 4) {
                float4 r4 = *(const float4*)(rp + jj);
                s[qi][jj + 0] += r4.x; s[qi][jj + 1] += r4.y;
                s[qi][jj + 2] += r4.z; s[qi][jj + 3] += r4.w;
            }
        }
#pragma unroll
        for (int qi = 0; qi < 2; qi++) {
            float cmax = s[qi][0];
#pragma unroll
            for (int jj = 1; jj < 16; jj++) cmax = fmaxf(cmax, s[qi][jj]);
            const float mn = fmaxf(m[qi], cmax);
            const float al = __expf(m[qi] - mn);
            m[qi] = mn;
            l[qi] *= al;
#pragma unroll
            for (int d = 0; d < HDIM; d++) o[qi][d] *= al;
            float ls = 0.f;
#pragma unroll
            for (int jj = 0; jj < 16; jj++) {
                const float p = __expf(s[qi][jj] - mn);
                s[qi][jj] = p;
                ls += p;
            }
            l[qi] += ls;
        }
#pragma unroll
        for (int jj = 0; jj < 16; jj++) {
            const float p0 = s[0][jj], p1 = s[1][jj];
            const float* vr = vn + (j0 + jj) * KVS;
#pragma unroll
            for (int d = 0; d < HDIM; d += 4) {
                float4 v4 = *(const float4*)(vr + d);
                o[0][d + 0] += p0 * v4.x; o[0][d + 1] += p0 * v4.y;
                o[0][d + 2] += p0 * v4.z; o[0][d + 3] += p0 * v4.w;
                o[1][d + 0] += p1 * v4.x; o[1][d + 1] += p1 * v4.y;
                o[1][d + 2] += p1 * v4.z; o[1][d + 3] += p1 * v4.w;
            }
        }
    }

#pragma unroll
    for (int qi = 0; qi < 2; qi++) {
        const float inv = 1.f / l[qi];
        const int r = t + qi * 128;
        float* op = g_attout + ((size_t)(b * NTOK + r)) * CDIM + h * HDIM;
#pragma unroll
        for (int d = 0; d < HDIM; d += 4) {
            float4 ov = make_float4(o[qi][d] * inv, o[qi][d + 1] * inv,
                                    o[qi][d + 2] * inv, o[qi][d + 3] * inv);
            *(float4*)(op + d) = ov;
        }
    }
}

// ---------------- launch ----------------
extern "C" void kernel_launch(void* const* d_in, const int* in_sizes, int n_in,
                              void* d_out, int out_size) {
    const float* x      = (const float*)d_in[0];
    const float* qkv_w  = (const float*)d_in[1];
    const float* q_bias = (const float*)d_in[2];
    const float* v_bias = (const float*)d_in[3];
    const float* lscale = (const float*)d_in[4];
    const float* cpb_w1 = (const float*)d_in[5];
    const float* cpb_b1 = (const float*)d_in[6];
    const float* cpb_w2 = (const float*)d_in[7];
    const float* proj_w = (const float*)d_in[8];
    const float* proj_b = (const float*)d_in[9];
    const float* table  = (const float*)d_in[10];
    const int*   rpi    = (const int*)d_in[11];
    float* out = (float*)d_out;

    cudaFuncSetAttribute(attn_kernel, cudaFuncAttributeMaxDynamicSharedMemorySize,
                         2 * NTOK * KVS * (int)sizeof(float));

    qkv_mma_kernel<<<dim3(9, 512), 256>>>(x, qkv_w, q_bias, v_bias);
    cpb_kernel<<<TBL, 128>>>(table, cpb_w1, cpb_b1, cpb_w2);
    rpb_kernel<<<NHEAD * NTOK, 256>>>(rpi);
    attn_kernel<<<BWIN * NHEAD, 128, 2 * NTOK * KVS * (int)sizeof(float)>>>(lscale);
    proj_mma_kernel<<<dim3(3, 512), 256>>>(proj_w, proj_b, out);
    (void)in_sizes; (void)n_in; (void)out_size;
}

// round 5
// speedup vs baseline: 2.2763x; 1.1945x over previous
#include <cuda_runtime.h>
#include <cuda_bf16.h>
#include <math.h>
#include <stdint.h>

// Problem constants
#define BWIN 256      // windows*batch
#define NTOK 256      // tokens per window
#define CDIM 384
#define NHEAD 12
#define HDIM 32
#define MROWS (BWIN*NTOK)   // 65536
#define TBL 961             // (2*16-1)^2
#define CPBH 512
#define LOG2E 1.44269504088896f

// ---------------- scratch (device globals; no allocs allowed) ----------------
__device__ float g_qkv[3ull * MROWS * CDIM];     // [3][M][384]
__device__ float g_attout[(size_t)MROWS * CDIM]; // [M][384]
__device__ float g_bt[TBL * NHEAD];              // raw cpb bias table
__device__ float g_rpb[(size_t)NHEAD * NTOK * NTOK]; // log2e*16*sigmoid(bt[rpi])

__device__ __forceinline__ uint32_t f2tf(float f) {
    uint32_t u;
    asm("cvt.rna.tf32.f32 %0, %1;" : "=r"(u) : "f"(f));
    return u;
}
__device__ __forceinline__ float ex2(float x) {
    float r;
    asm("ex2.approx.ftz.f32 %0, %1;" : "=f"(r) : "f"(x));
    return r;
}
__device__ __forceinline__ void mma_tf32(float* c, const uint32_t* a, const uint32_t* b) {
    asm volatile(
        "mma.sync.aligned.m16n8k8.row.col.f32.tf32.tf32.f32 "
        "{%0,%1,%2,%3}, {%4,%5,%6,%7}, {%8,%9}, {%0,%1,%2,%3};\n"
        : "+f"(c[0]), "+f"(c[1]), "+f"(c[2]), "+f"(c[3])
        : "r"(a[0]), "r"(a[1]), "r"(a[2]), "r"(a[3]), "r"(b[0]), "r"(b[1]));
}

// ==================== tf32 tensor-core GEMM (unchanged from R2) ====================
#define ASTR 20

__device__ __forceinline__ void mma_gemm_core(
    const float* __restrict__ Ag, const float* __restrict__ Bg,
    float acc[4][4][4]) {
    __shared__ uint32_t As[2][128 * ASTR];
    __shared__ uint32_t Bs[2][128 * ASTR];

    const int tid = threadIdx.x;
    const int lane = tid & 31;
    const int wm = ((tid >> 5) >> 2) * 64;
    const int wn = ((tid >> 5) & 3) * 32;
    const int lr = tid >> 2;
    const int lq = (tid & 3) * 4;
    const int g = lane >> 2;
    const int tg = lane & 3;

    float4 pa0, pa1, pb0, pb1;
    pa0 = *(const float4*)(Ag + (size_t)lr * CDIM + lq);
    pa1 = *(const float4*)(Ag + (size_t)(lr + 64) * CDIM + lq);
    pb0 = *(const float4*)(Bg + (size_t)lr * CDIM + lq);
    pb1 = *(const float4*)(Bg + (size_t)(lr + 64) * CDIM + lq);
    {
        uint4 u;
        u.x = f2tf(pa0.x); u.y = f2tf(pa0.y); u.z = f2tf(pa0.z); u.w = f2tf(pa0.w);
        *(uint4*)&As[0][lr * ASTR + lq] = u;
        u.x = f2tf(pa1.x); u.y = f2tf(pa1.y); u.z = f2tf(pa1.z); u.w = f2tf(pa1.w);
        *(uint4*)&As[0][(lr + 64) * ASTR + lq] = u;
        u.x = f2tf(pb0.x); u.y = f2tf(pb0.y); u.z = f2tf(pb0.z); u.w = f2tf(pb0.w);
        *(uint4*)&Bs[0][lr * ASTR + lq] = u;
        u.x = f2tf(pb1.x); u.y = f2tf(pb1.y); u.z = f2tf(pb1.z); u.w = f2tf(pb1.w);
        *(uint4*)&Bs[0][(lr + 64) * ASTR + lq] = u;
    }
    __syncthreads();

    int cur = 0;
    const int NCHUNK = CDIM / 16;
#pragma unroll 1
    for (int c = 0; c < NCHUNK; c++) {
        if (c + 1 < NCHUNK) {
            const int k0 = (c + 1) * 16;
            pa0 = *(const float4*)(Ag + (size_t)lr * CDIM + k0 + lq);
            pa1 = *(const float4*)(Ag + (size_t)(lr + 64) * CDIM + k0 + lq);
            pb0 = *(const float4*)(Bg + (size_t)lr * CDIM + k0 + lq);
            pb1 = *(const float4*)(Bg + (size_t)(lr + 64) * CDIM + k0 + lq);
        }
#pragma unroll
        for (int ks = 0; ks < 2; ks++) {
            const int kk = ks * 8 + tg;
            uint32_t a[4][4], b[4][2];
#pragma unroll
            for (int mt = 0; mt < 4; mt++) {
                const int row = wm + mt * 16 + g;
                a[mt][0] = As[cur][row * ASTR + kk];
                a[mt][1] = As[cur][(row + 8) * ASTR + kk];
                a[mt][2] = As[cur][row * ASTR + kk + 4];
                a[mt][3] = As[cur][(row + 8) * ASTR + kk + 4];
            }
#pragma unroll
            for (int nt = 0; nt < 4; nt++) {
                const int col = wn + nt * 8 + g;
                b[nt][0] = Bs[cur][col * ASTR + kk];
                b[nt][1] = Bs[cur][col * ASTR + kk + 4];
            }
#pragma unroll
            for (int mt = 0; mt < 4; mt++)
#pragma unroll
                for (int nt = 0; nt < 4; nt++)
                    mma_tf32(acc[mt][nt], a[mt], b[nt]);
        }
        if (c + 1 < NCHUNK) {
            const int nb = cur ^ 1;
            uint4 u;
            u.x = f2tf(pa0.x); u.y = f2tf(pa0.y); u.z = f2tf(pa0.z); u.w = f2tf(pa0.w);
            *(uint4*)&As[nb][lr * ASTR + lq] = u;
            u.x = f2tf(pa1.x); u.y = f2tf(pa1.y); u.z = f2tf(pa1.z); u.w = f2tf(pa1.w);
            *(uint4*)&As[nb][(lr + 64) * ASTR + lq] = u;
            u.x = f2tf(pb0.x); u.y = f2tf(pb0.y); u.z = f2tf(pb0.z); u.w = f2tf(pb0.w);
            *(uint4*)&Bs[nb][lr * ASTR + lq] = u;
            u.x = f2tf(pb1.x); u.y = f2tf(pb1.y); u.z = f2tf(pb1.z); u.w = f2tf(pb1.w);
            *(uint4*)&Bs[nb][(lr + 64) * ASTR + lq] = u;
        }
        __syncthreads();
        cur ^= 1;
    }
}

__global__ __launch_bounds__(256) void qkv_mma_kernel(
    const float* __restrict__ x, const float* __restrict__ w,
    const float* __restrict__ qb, const float* __restrict__ vb) {
    float acc[4][4][4];
#pragma unroll
    for (int i = 0; i < 4; i++)
#pragma unroll
        for (int j = 0; j < 4; j++)
#pragma unroll
            for (int k = 0; k < 4; k++) acc[i][j][k] = 0.f;

    const float* Ag = x + (size_t)blockIdx.y * 128 * CDIM;
    const float* Bg = w + (size_t)blockIdx.x * 128 * CDIM;
    mma_gemm_core(Ag, Bg, acc);

    const int tid = threadIdx.x;
    const int lane = tid & 31;
    const int wm = ((tid >> 5) >> 2) * 64;
    const int wn = ((tid >> 5) & 3) * 32;
    const int g = lane >> 2, tg = lane & 3;

    const int nbase = blockIdx.x * 128;
    const int which = nbase / CDIM;
    const int cb = nbase % CDIM;
    float* outp = g_qkv + (size_t)which * MROWS * CDIM;

#pragma unroll
    for (int mt = 0; mt < 4; mt++) {
        const int row = blockIdx.y * 128 + wm + mt * 16 + g;
#pragma unroll
        for (int nt = 0; nt < 4; nt++) {
            const int col = cb + wn + nt * 8 + 2 * tg;
            float b0 = 0.f, b1 = 0.f;
            if (which == 0) { b0 = qb[col]; b1 = qb[col + 1]; }
            else if (which == 2) { b0 = vb[col]; b1 = vb[col + 1]; }
            float2 o0 = make_float2(acc[mt][nt][0] + b0, acc[mt][nt][1] + b1);
            float2 o1 = make_float2(acc[mt][nt][2] + b0, acc[mt][nt][3] + b1);
            *(float2*)(outp + (size_t)row * CDIM + col) = o0;
            *(float2*)(outp + (size_t)(row + 8) * CDIM + col) = o1;
        }
    }
}

__global__ __launch_bounds__(256) void proj_mma_kernel(
    const float* __restrict__ w, const float* __restrict__ pb,
    float* __restrict__ out) {
    float acc[4][4][4];
#pragma unroll
    for (int i = 0; i < 4; i++)
#pragma unroll
        for (int j = 0; j < 4; j++)
#pragma unroll
            for (int k = 0; k < 4; k++) acc[i][j][k] = 0.f;

    const float* Ag = g_attout + (size_t)blockIdx.y * 128 * CDIM;
    const float* Bg = w + (size_t)blockIdx.x * 128 * CDIM;
    mma_gemm_core(Ag, Bg, acc);

    const int tid = threadIdx.x;
    const int lane = tid & 31;
    const int wm = ((tid >> 5) >> 2) * 64;
    const int wn = ((tid >> 5) & 3) * 32;
    const int g = lane >> 2, tg = lane & 3;
    const int nbase = blockIdx.x * 128;

#pragma unroll
    for (int mt = 0; mt < 4; mt++) {
        const int row = blockIdx.y * 128 + wm + mt * 16 + g;
#pragma unroll
        for (int nt = 0; nt < 4; nt++) {
            const int col = nbase + wn + nt * 8 + 2 * tg;
            const float b0 = pb[col], b1 = pb[col + 1];
            float2 o0 = make_float2(acc[mt][nt][0] + b0, acc[mt][nt][1] + b1);
            float2 o1 = make_float2(acc[mt][nt][2] + b0, acc[mt][nt][3] + b1);
            *(float2*)(out + (size_t)row * CDIM + col) = o0;
            *(float2*)(out + (size_t)(row + 8) * CDIM + col) = o1;
        }
    }
}

// ---------------- CPB MLP ----------------
__global__ __launch_bounds__(128) void cpb_kernel(
    const float* __restrict__ table, const float* __restrict__ w1,
    const float* __restrict__ b1, const float* __restrict__ w2) {
    __shared__ float hid[CPBH];
    __shared__ float part[NHEAD][9];
    const int r = blockIdx.x;
    const float t0 = table[r * 2 + 0];
    const float t1 = table[r * 2 + 1];
    for (int j = threadIdx.x; j < CPBH; j += 128)
        hid[j] = fmaxf(w1[j * 2] * t0 + w1[j * 2 + 1] * t1 + b1[j], 0.f);
    __syncthreads();
    const int t = threadIdx.x;
    if (t < 96) {
        const int h = t >> 3, seg = t & 7;
        float s = 0.f;
        const float* wr = w2 + h * CPBH + seg * 64;
        const float* hr = hid + seg * 64;
#pragma unroll 8
        for (int j = 0; j < 64; j++) s += hr[j] * wr[j];
        part[h][seg] = s;
    }
    __syncthreads();
    if (t < NHEAD) {
        float s = 0.f;
#pragma unroll
        for (int seg = 0; seg < 8; seg++) s += part[t][seg];
        g_bt[r * NHEAD + t] = s;
    }
}

// rpb pre-scaled by log2e so attention can use exp2 directly
__global__ __launch_bounds__(256) void rpb_kernel(const int* __restrict__ rpi) {
    const int h = blockIdx.x >> 8;
    const int i = blockIdx.x & 255;
    const int j = threadIdx.x;
    const int idx = rpi[i * NTOK + j];
    const float v = g_bt[idx * NHEAD + h];
    g_rpb[((size_t)(h * NTOK + i)) * NTOK + j] = LOG2E * 16.f / (1.f + __expf(-v));
}

// ============== tensor-core attention: one CTA (256 thr) per (window, head) ==============
// 8 warps, warp w owns query rows [32w, 32w+32). No max-subtraction needed
// (logits bounded by scale+16). PV uses 3-pass hi/lo split for accuracy.
#define KSTR 36
#define VSTR 40
#define PSTR 36
#define OFF_VH (256*KSTR)
#define OFF_VL (OFF_VH + 256*VSTR)
#define OFF_PH (OFF_VL + 256*VSTR)
#define OFF_PL (OFF_PH + 256*PSTR)
#define ATTN_SMEM_WORDS (OFF_PL + 256*PSTR)

__global__ __launch_bounds__(256) void attn_mma_kernel(const float* __restrict__ lscale) {
    extern __shared__ uint32_t smu[];
    uint32_t* Ks = smu;
    uint32_t* Vh = smu + OFF_VH;
    uint32_t* Vl = smu + OFF_VL;
    uint32_t* Ph = smu + OFF_PH;
    uint32_t* Pl = smu + OFF_PL;

    const int b = blockIdx.x / NHEAD;
    const int h = blockIdx.x % NHEAD;
    const int tid = threadIdx.x;
    const int lane = tid & 31;
    const int g = lane >> 2, tg = lane & 3;
    const int wm = (tid >> 5) * 32;

    const size_t base = ((size_t)b * NTOK) * CDIM + h * HDIM;
    const float* gq = g_qkv + base;
    const float* gk = g_qkv + (size_t)MROWS * CDIM + base;
    const float* gv = g_qkv + 2ull * MROWS * CDIM + base;
    const float scale2 = __expf(fminf(lscale[h], 4.60517018598809f)) * LOG2E;

    // ---- load phase: thread r handles row r of k, v, q ----
    {
        const int r = tid;
        float tv[32];
        const float* kr = gk + (size_t)r * CDIM;
#pragma unroll
        for (int d = 0; d < HDIM; d += 4) *(float4*)(tv + d) = *(const float4*)(kr + d);
        float ss = 0.f;
#pragma unroll
        for (int d = 0; d < HDIM; d++) ss += tv[d] * tv[d];
        float rn = 1.f / fmaxf(sqrtf(ss), 1e-12f);
#pragma unroll
        for (int d = 0; d < HDIM; d += 4) {
            uint4 u = make_uint4(f2tf(tv[d] * rn), f2tf(tv[d + 1] * rn),
                                 f2tf(tv[d + 2] * rn), f2tf(tv[d + 3] * rn));
            *(uint4*)&Ks[r * KSTR + d] = u;
        }
        const float* vr = gv + (size_t)r * CDIM;
#pragma unroll
        for (int d = 0; d < HDIM; d += 4) *(float4*)(tv + d) = *(const float4*)(vr + d);
#pragma unroll
        for (int d = 0; d < HDIM; d += 4) {
            uint4 uh, ul;
            uh.x = f2tf(tv[d]);     ul.x = f2tf(tv[d]     - __uint_as_float(uh.x));
            uh.y = f2tf(tv[d + 1]); ul.y = f2tf(tv[d + 1] - __uint_as_float(uh.y));
            uh.z = f2tf(tv[d + 2]); ul.z = f2tf(tv[d + 2] - __uint_as_float(uh.z));
            uh.w = f2tf(tv[d + 3]); ul.w = f2tf(tv[d + 3] - __uint_as_float(uh.w));
            *(uint4*)&Vh[r * VSTR + d] = uh;
            *(uint4*)&Vl[r * VSTR + d] = ul;
        }
        const float* qr = gq + (size_t)r * CDIM;
#pragma unroll
        for (int d = 0; d < HDIM; d += 4) *(float4*)(tv + d) = *(const float4*)(qr + d);
        ss = 0.f;
#pragma unroll
        for (int d = 0; d < HDIM; d++) ss += tv[d] * tv[d];
        rn = scale2 / fmaxf(sqrtf(ss), 1e-12f);
#pragma unroll
        for (int d = 0; d < HDIM; d += 4) {
            uint4 u = make_uint4(f2tf(tv[d] * rn), f2tf(tv[d + 1] * rn),
                                 f2tf(tv[d + 2] * rn), f2tf(tv[d + 3] * rn));
            *(uint4*)&Ph[r * PSTR + d] = u;  // q staged in Ph (own-warp rows)
        }
    }
    __syncthreads();

    // ---- extract q A-fragments (kept in regs whole kernel) ----
    uint32_t qa[2][4][4];  // [mtile][kstep][frag]
#pragma unroll
    for (int mt = 0; mt < 2; mt++)
#pragma unroll
        for (int ks = 0; ks < 4; ks++) {
            const int row = wm + mt * 16 + g;
            const int kk = ks * 8 + tg;
            qa[mt][ks][0] = Ph[row * PSTR + kk];
            qa[mt][ks][1] = Ph[(row + 8) * PSTR + kk];
            qa[mt][ks][2] = Ph[row * PSTR + kk + 4];
            qa[mt][ks][3] = Ph[(row + 8) * PSTR + kk + 4];
        }
    __syncwarp();

    float oa[2][4][4];
    float lsum[2][2];
#pragma unroll
    for (int mt = 0; mt < 2; mt++) {
        lsum[mt][0] = 0.f; lsum[mt][1] = 0.f;
#pragma unroll
        for (int dt = 0; dt < 4; dt++)
#pragma unroll
            for (int i = 0; i < 4; i++) oa[mt][dt][i] = 0.f;
    }

    const float* rpbh = g_rpb + (size_t)h * NTOK * NTOK;

#pragma unroll 1
    for (int j0 = 0; j0 < NTOK; j0 += 32) {
        // ---- S = Qn @ Kn^T (scaled) ----
        float sc[2][4][4];
#pragma unroll
        for (int mt = 0; mt < 2; mt++)
#pragma unroll
            for (int nt = 0; nt < 4; nt++)
#pragma unroll
                for (int i = 0; i < 4; i++) sc[mt][nt][i] = 0.f;
#pragma unroll
        for (int ks = 0; ks < 4; ks++) {
            const int kk = ks * 8 + tg;
            uint32_t kb[4][2];
#pragma unroll
            for (int nt = 0; nt < 4; nt++) {
                const uint32_t* kp = Ks + (j0 + nt * 8 + g) * KSTR + kk;
                kb[nt][0] = kp[0];
                kb[nt][1] = kp[4];
            }
#pragma unroll
            for (int mt = 0; mt < 2; mt++)
#pragma unroll
                for (int nt = 0; nt < 4; nt++)
                    mma_tf32(sc[mt][nt], qa[mt][ks], kb[nt]);
        }
        // ---- + rpb, exp2, accumulate l, split P hi/lo into smem ----
#pragma unroll
        for (int mt = 0; mt < 2; mt++) {
            const int row = wm + mt * 16 + g;
#pragma unroll
            for (int nt = 0; nt < 4; nt++) {
                const int col = j0 + nt * 8 + 2 * tg;
                const float2 r0 = *(const float2*)(rpbh + (size_t)row * NTOK + col);
                const float2 r1 = *(const float2*)(rpbh + (size_t)(row + 8) * NTOK + col);
                const float p0 = ex2(sc[mt][nt][0] + r0.x);
                const float p1 = ex2(sc[mt][nt][1] + r0.y);
                const float p2 = ex2(sc[mt][nt][2] + r1.x);
                const float p3 = ex2(sc[mt][nt][3] + r1.y);
                lsum[mt][0] += p0 + p1;
                lsum[mt][1] += p2 + p3;
                uint2 uh0, ul0, uh1, ul1;
                uh0.x = f2tf(p0); ul0.x = f2tf(p0 - __uint_as_float(uh0.x));
                uh0.y = f2tf(p1); ul0.y = f2tf(p1 - __uint_as_float(uh0.y));
                uh1.x = f2tf(p2); ul1.x = f2tf(p2 - __uint_as_float(uh1.x));
                uh1.y = f2tf(p3); ul1.y = f2tf(p3 - __uint_as_float(uh1.y));
                const int pc = nt * 8 + 2 * tg;
                *(uint2*)&Ph[row * PSTR + pc] = uh0;
                *(uint2*)&Ph[(row + 8) * PSTR + pc] = uh1;
                *(uint2*)&Pl[row * PSTR + pc] = ul0;
                *(uint2*)&Pl[(row + 8) * PSTR + pc] = ul1;
            }
        }
        __syncwarp();
        // ---- O += P @ V (3-pass: Ph*Vh + Pl*Vh + Ph*Vl) ----
#pragma unroll
        for (int ks = 0; ks < 4; ks++) {
            const int kk = ks * 8 + tg;
            uint32_t pah[2][4], pal[2][4], vbh[4][2], vbl[4][2];
#pragma unroll
            for (int mt = 0; mt < 2; mt++) {
                const uint32_t* pp = Ph + (wm + mt * 16 + g) * PSTR + kk;
                pah[mt][0] = pp[0];
                pah[mt][1] = pp[8 * PSTR];
                pah[mt][2] = pp[4];
                pah[mt][3] = pp[8 * PSTR + 4];
                const uint32_t* pq = Pl + (wm + mt * 16 + g) * PSTR + kk;
                pal[mt][0] = pq[0];
                pal[mt][1] = pq[8 * PSTR];
                pal[mt][2] = pq[4];
                pal[mt][3] = pq[8 * PSTR + 4];
            }
#pragma unroll
            for (int dt = 0; dt < 4; dt++) {
                const uint32_t* vp = Vh + (j0 + kk) * VSTR + dt * 8 + g;
                vbh[dt][0] = vp[0];
                vbh[dt][1] = vp[4 * VSTR];
                const uint32_t* vq = Vl + (j0 + kk) * VSTR + dt * 8 + g;
                vbl[dt][0] = vq[0];
                vbl[dt][1] = vq[4 * VSTR];
            }
#pragma unroll
            for (int mt = 0; mt < 2; mt++)
#pragma unroll
                for (int dt = 0; dt < 4; dt++) {
                    mma_tf32(oa[mt][dt], pah[mt], vbh[dt]);
                    mma_tf32(oa[mt][dt], pal[mt], vbh[dt]);
                    mma_tf32(oa[mt][dt], pah[mt], vbl[dt]);
                }
        }
        __syncwarp();
    }

    // ---- finalize: row sums across the 4-lane quad, scale, store ----
    float inv[2][2];
#pragma unroll
    for (int mt = 0; mt < 2; mt++)
#pragma unroll
        for (int hh = 0; hh < 2; hh++) {
            float s = lsum[mt][hh];
            s += __shfl_xor_sync(0xffffffffu, s, 1);
            s += __shfl_xor_sync(0xffffffffu, s, 2);
            inv[mt][hh] = 1.f / s;
        }
#pragma unroll
    for (int mt = 0; mt < 2; mt++) {
        const int row = wm + mt * 16 + g;
#pragma unroll
        for (int dt = 0; dt < 4; dt++) {
            const int col = h * HDIM + dt * 8 + 2 * tg;
            float2 o0 = make_float2(oa[mt][dt][0] * inv[mt][0], oa[mt][dt][1] * inv[mt][0]);
            float2 o1 = make_float2(oa[mt][dt][2] * inv[mt][1], oa[mt][dt][3] * inv[mt][1]);
            *(float2*)(g_attout + ((size_t)(b * NTOK + row)) * CDIM + col) = o0;
            *(float2*)(g_attout + ((size_t)(b * NTOK + row + 8)) * CDIM + col) = o1;
        }
    }
}

// ---------------- launch ----------------
extern "C" void kernel_launch(void* const* d_in, const int* in_sizes, int n_in,
                              void* d_out, int out_size) {
    const float* x      = (const float*)d_in[0];
    const float* qkv_w  = (const float*)d_in[1];
    const float* q_bias = (const float*)d_in[2];
    const float* v_bias = (const float*)d_in[3];
    const float* lscale = (const float*)d_in[4];
    const float* cpb_w1 = (const float*)d_in[5];
    const float* cpb_b1 = (const float*)d_in[6];
    const float* cpb_w2 = (const float*)d_in[7];
    const float* proj_w = (const float*)d_in[8];
    const float* proj_b = (const float*)d_in[9];
    const float* table  = (const float*)d_in[10];
    const int*   rpi    = (const int*)d_in[11];
    float* out = (float*)d_out;

    const int attn_smem = ATTN_SMEM_WORDS * (int)sizeof(uint32_t);  // 192512 B
    cudaFuncSetAttribute(attn_mma_kernel, cudaFuncAttributeMaxDynamicSharedMemorySize,
                         attn_smem);

    qkv_mma_kernel<<<dim3(9, 512), 256>>>(x, qkv_w, q_bias, v_bias);
    cpb_kernel<<<TBL, 128>>>(table, cpb_w1, cpb_b1, cpb_w2);
    rpb_kernel<<<NHEAD * NTOK, 256>>>(rpi);
    attn_mma_kernel<<<BWIN * NHEAD, 256, attn_smem>>>(lscale);
    proj_mma_kernel<<<dim3(3, 512), 256>>>(proj_w, proj_b, out);
    (void)in_sizes; (void)n_in; (void)out_size;
}

// round 6
// speedup vs baseline: 2.7658x; 1.2150x over previous
#include <cuda_runtime.h>
#include <cuda_bf16.h>
#include <math.h>
#include <stdint.h>

// Problem constants
#define BWIN 256      // windows*batch
#define NTOK 256      // tokens per window
#define CDIM 384
#define NHEAD 12
#define HDIM 32
#define MROWS (BWIN*NTOK)   // 65536
#define TBL 961             // (2*16-1)^2
#define CPBH 512
#define LOG2E 1.44269504088896f

// ---------------- scratch (device globals; no allocs allowed) ----------------
__device__ float g_qkv[3ull * MROWS * CDIM];     // [3][M][384]
__device__ float g_attout[(size_t)MROWS * CDIM]; // [M][384]
__device__ float g_bt[TBL * NHEAD];              // raw cpb bias table
__device__ float g_rpb[(size_t)NHEAD * NTOK * NTOK]; // log2e*16*sigmoid(bt[rpi])

__device__ __forceinline__ uint32_t f2tf(float f) {
    uint32_t u;
    asm("cvt.rna.tf32.f32 %0, %1;" : "=r"(u) : "f"(f));
    return u;
}
__device__ __forceinline__ float ex2(float x) {
    float r;
    asm("ex2.approx.ftz.f32 %0, %1;" : "=f"(r) : "f"(x));
    return r;
}
__device__ __forceinline__ void mma_tf32(float* c, const uint32_t* a, const uint32_t* b) {
    asm volatile(
        "mma.sync.aligned.m16n8k8.row.col.f32.tf32.tf32.f32 "
        "{%0,%1,%2,%3}, {%4,%5,%6,%7}, {%8,%9}, {%0,%1,%2,%3};\n"
        : "+f"(c[0]), "+f"(c[1]), "+f"(c[2]), "+f"(c[3])
        : "r"(a[0]), "r"(a[1]), "r"(a[2]), "r"(a[3]), "r"(b[0]), "r"(b[1]));
}
__device__ __forceinline__ void mma_bf16(float* c, const uint32_t* a, const uint32_t* b) {
    asm volatile(
        "mma.sync.aligned.m16n8k16.row.col.f32.bf16.bf16.f32 "
        "{%0,%1,%2,%3}, {%4,%5,%6,%7}, {%8,%9}, {%0,%1,%2,%3};\n"
        : "+f"(c[0]), "+f"(c[1]), "+f"(c[2]), "+f"(c[3])
        : "r"(a[0]), "r"(a[1]), "r"(a[2]), "r"(a[3]), "r"(b[0]), "r"(b[1]));
}
// pack two floats into bf16x2 word (lo half = x, hi half = y) + hi/lo split
__device__ __forceinline__ void hilo_pack(float x, float y, uint32_t& wh, uint32_t& wl) {
    __nv_bfloat16 hx = __float2bfloat16(x);
    __nv_bfloat16 hy = __float2bfloat16(y);
    __nv_bfloat16 lx = __float2bfloat16(x - __bfloat162float(hx));
    __nv_bfloat16 ly = __float2bfloat16(y - __bfloat162float(hy));
    wh = (uint32_t)__bfloat16_as_ushort(hx) | ((uint32_t)__bfloat16_as_ushort(hy) << 16);
    wl = (uint32_t)__bfloat16_as_ushort(lx) | ((uint32_t)__bfloat16_as_ushort(ly) << 16);
}

// ==================== tf32 tensor-core GEMM (unchanged) ====================
#define ASTR 20

__device__ __forceinline__ void mma_gemm_core(
    const float* __restrict__ Ag, const float* __restrict__ Bg,
    float acc[4][4][4]) {
    __shared__ uint32_t As[2][128 * ASTR];
    __shared__ uint32_t Bs[2][128 * ASTR];

    const int tid = threadIdx.x;
    const int lane = tid & 31;
    const int wm = ((tid >> 5) >> 2) * 64;
    const int wn = ((tid >> 5) & 3) * 32;
    const int lr = tid >> 2;
    const int lq = (tid & 3) * 4;
    const int g = lane >> 2;
    const int tg = lane & 3;

    float4 pa0, pa1, pb0, pb1;
    pa0 = *(const float4*)(Ag + (size_t)lr * CDIM + lq);
    pa1 = *(const float4*)(Ag + (size_t)(lr + 64) * CDIM + lq);
    pb0 = *(const float4*)(Bg + (size_t)lr * CDIM + lq);
    pb1 = *(const float4*)(Bg + (size_t)(lr + 64) * CDIM + lq);
    {
        uint4 u;
        u.x = f2tf(pa0.x); u.y = f2tf(pa0.y); u.z = f2tf(pa0.z); u.w = f2tf(pa0.w);
        *(uint4*)&As[0][lr * ASTR + lq] = u;
        u.x = f2tf(pa1.x); u.y = f2tf(pa1.y); u.z = f2tf(pa1.z); u.w = f2tf(pa1.w);
        *(uint4*)&As[0][(lr + 64) * ASTR + lq] = u;
        u.x = f2tf(pb0.x); u.y = f2tf(pb0.y); u.z = f2tf(pb0.z); u.w = f2tf(pb0.w);
        *(uint4*)&Bs[0][lr * ASTR + lq] = u;
        u.x = f2tf(pb1.x); u.y = f2tf(pb1.y); u.z = f2tf(pb1.z); u.w = f2tf(pb1.w);
        *(uint4*)&Bs[0][(lr + 64) * ASTR + lq] = u;
    }
    __syncthreads();

    int cur = 0;
    const int NCHUNK = CDIM / 16;
#pragma unroll 1
    for (int c = 0; c < NCHUNK; c++) {
        if (c + 1 < NCHUNK) {
            const int k0 = (c + 1) * 16;
            pa0 = *(const float4*)(Ag + (size_t)lr * CDIM + k0 + lq);
            pa1 = *(const float4*)(Ag + (size_t)(lr + 64) * CDIM + k0 + lq);
            pb0 = *(const float4*)(Bg + (size_t)lr * CDIM + k0 + lq);
            pb1 = *(const float4*)(Bg + (size_t)(lr + 64) * CDIM + k0 + lq);
        }
#pragma unroll
        for (int ks = 0; ks < 2; ks++) {
            const int kk = ks * 8 + tg;
            uint32_t a[4][4], b[4][2];
#pragma unroll
            for (int mt = 0; mt < 4; mt++) {
                const int row = wm + mt * 16 + g;
                a[mt][0] = As[cur][row * ASTR + kk];
                a[mt][1] = As[cur][(row + 8) * ASTR + kk];
                a[mt][2] = As[cur][row * ASTR + kk + 4];
                a[mt][3] = As[cur][(row + 8) * ASTR + kk + 4];
            }
#pragma unroll
            for (int nt = 0; nt < 4; nt++) {
                const int col = wn + nt * 8 + g;
                b[nt][0] = Bs[cur][col * ASTR + kk];
                b[nt][1] = Bs[cur][col * ASTR + kk + 4];
            }
#pragma unroll
            for (int mt = 0; mt < 4; mt++)
#pragma unroll
                for (int nt = 0; nt < 4; nt++)
                    mma_tf32(acc[mt][nt], a[mt], b[nt]);
        }
        if (c + 1 < NCHUNK) {
            const int nb = cur ^ 1;
            uint4 u;
            u.x = f2tf(pa0.x); u.y = f2tf(pa0.y); u.z = f2tf(pa0.z); u.w = f2tf(pa0.w);
            *(uint4*)&As[nb][lr * ASTR + lq] = u;
            u.x = f2tf(pa1.x); u.y = f2tf(pa1.y); u.z = f2tf(pa1.z); u.w = f2tf(pa1.w);
            *(uint4*)&As[nb][(lr + 64) * ASTR + lq] = u;
            u.x = f2tf(pb0.x); u.y = f2tf(pb0.y); u.z = f2tf(pb0.z); u.w = f2tf(pb0.w);
            *(uint4*)&Bs[nb][lr * ASTR + lq] = u;
            u.x = f2tf(pb1.x); u.y = f2tf(pb1.y); u.z = f2tf(pb1.z); u.w = f2tf(pb1.w);
            *(uint4*)&Bs[nb][(lr + 64) * ASTR + lq] = u;
        }
        __syncthreads();
        cur ^= 1;
    }
}

__global__ __launch_bounds__(256) void qkv_mma_kernel(
    const float* __restrict__ x, const float* __restrict__ w,
    const float* __restrict__ qb, const float* __restrict__ vb) {
    float acc[4][4][4];
#pragma unroll
    for (int i = 0; i < 4; i++)
#pragma unroll
        for (int j = 0; j < 4; j++)
#pragma unroll
            for (int k = 0; k < 4; k++) acc[i][j][k] = 0.f;

    const float* Ag = x + (size_t)blockIdx.y * 128 * CDIM;
    const float* Bg = w + (size_t)blockIdx.x * 128 * CDIM;
    mma_gemm_core(Ag, Bg, acc);

    const int tid = threadIdx.x;
    const int lane = tid & 31;
    const int wm = ((tid >> 5) >> 2) * 64;
    const int wn = ((tid >> 5) & 3) * 32;
    const int g = lane >> 2, tg = lane & 3;

    const int nbase = blockIdx.x * 128;
    const int which = nbase / CDIM;
    const int cb = nbase % CDIM;
    float* outp = g_qkv + (size_t)which * MROWS * CDIM;

#pragma unroll
    for (int mt = 0; mt < 4; mt++) {
        const int row = blockIdx.y * 128 + wm + mt * 16 + g;
#pragma unroll
        for (int nt = 0; nt < 4; nt++) {
            const int col = cb + wn + nt * 8 + 2 * tg;
            float b0 = 0.f, b1 = 0.f;
            if (which == 0) { b0 = qb[col]; b1 = qb[col + 1]; }
            else if (which == 2) { b0 = vb[col]; b1 = vb[col + 1]; }
            float2 o0 = make_float2(acc[mt][nt][0] + b0, acc[mt][nt][1] + b1);
            float2 o1 = make_float2(acc[mt][nt][2] + b0, acc[mt][nt][3] + b1);
            *(float2*)(outp + (size_t)row * CDIM + col) = o0;
            *(float2*)(outp + (size_t)(row + 8) * CDIM + col) = o1;
        }
    }
}

__global__ __launch_bounds__(256) void proj_mma_kernel(
    const float* __restrict__ w, const float* __restrict__ pb,
    float* __restrict__ out) {
    float acc[4][4][4];
#pragma unroll
    for (int i = 0; i < 4; i++)
#pragma unroll
        for (int j = 0; j < 4; j++)
#pragma unroll
            for (int k = 0; k < 4; k++) acc[i][j][k] = 0.f;

    const float* Ag = g_attout + (size_t)blockIdx.y * 128 * CDIM;
    const float* Bg = w + (size_t)blockIdx.x * 128 * CDIM;
    mma_gemm_core(Ag, Bg, acc);

    const int tid = threadIdx.x;
    const int lane = tid & 31;
    const int wm = ((tid >> 5) >> 2) * 64;
    const int wn = ((tid >> 5) & 3) * 32;
    const int g = lane >> 2, tg = lane & 3;
    const int nbase = blockIdx.x * 128;

#pragma unroll
    for (int mt = 0; mt < 4; mt++) {
        const int row = blockIdx.y * 128 + wm + mt * 16 + g;
#pragma unroll
        for (int nt = 0; nt < 4; nt++) {
            const int col = nbase + wn + nt * 8 + 2 * tg;
            const float b0 = pb[col], b1 = pb[col + 1];
            float2 o0 = make_float2(acc[mt][nt][0] + b0, acc[mt][nt][1] + b1);
            float2 o1 = make_float2(acc[mt][nt][2] + b0, acc[mt][nt][3] + b1);
            *(float2*)(out + (size_t)row * CDIM + col) = o0;
            *(float2*)(out + (size_t)(row + 8) * CDIM + col) = o1;
        }
    }
}

// ---------------- CPB MLP ----------------
__global__ __launch_bounds__(128) void cpb_kernel(
    const float* __restrict__ table, const float* __restrict__ w1,
    const float* __restrict__ b1, const float* __restrict__ w2) {
    __shared__ float hid[CPBH];
    __shared__ float part[NHEAD][9];
    const int r = blockIdx.x;
    const float t0 = table[r * 2 + 0];
    const float t1 = table[r * 2 + 1];
    for (int j = threadIdx.x; j < CPBH; j += 128)
        hid[j] = fmaxf(w1[j * 2] * t0 + w1[j * 2 + 1] * t1 + b1[j], 0.f);
    __syncthreads();
    const int t = threadIdx.x;
    if (t < 96) {
        const int h = t >> 3, seg = t & 7;
        float s = 0.f;
        const float* wr = w2 + h * CPBH + seg * 64;
        const float* hr = hid + seg * 64;
#pragma unroll 8
        for (int j = 0; j < 64; j++) s += hr[j] * wr[j];
        part[h][seg] = s;
    }
    __syncthreads();
    if (t < NHEAD) {
        float s = 0.f;
#pragma unroll
        for (int seg = 0; seg < 8; seg++) s += part[t][seg];
        g_bt[r * NHEAD + t] = s;
    }
}

// rpb pre-scaled by log2e so attention can use exp2 directly
__global__ __launch_bounds__(256) void rpb_kernel(const int* __restrict__ rpi) {
    const int h = blockIdx.x >> 8;
    const int i = blockIdx.x & 255;
    const int j = threadIdx.x;
    const int idx = rpi[i * NTOK + j];
    const float v = g_bt[idx * NHEAD + h];
    g_rpb[((size_t)(h * NTOK + i)) * NTOK + j] = LOG2E * 16.f / (1.f + __expf(-v));
}

// ============== bf16-split tensor-core attention ==============
// One CTA (256 thr, 8 warps) per (window, head); warp w owns query rows [32w,32w+32).
// P lives entirely in registers: m16n8k16 C-fragment == next A-fragment.
// 3-term bf16 splits: S = Qh Kh + Qh Kl + Ql Kh ; O += Ph Vh + Pl Vh + Ph Vl.
#define KSW 20                          // K row stride in bf16x2 words (16 data + 4 pad)
#define VSW 132                         // Vt row stride in bf16x2 words (128 + 4 pad)
#define OFF_KLO (256*KSW)               // 5120
#define OFF_VTHI (2*256*KSW)            // 10240
#define OFF_VTLO (OFF_VTHI + 32*VSW)    // 14464
#define OFF_RN  (OFF_VTLO + 32*VSW)     // 18688
#define ATTN_WORDS (OFF_RN + 256)       // 18944 words = 75776 bytes

__global__ __launch_bounds__(256, 2) void attn_bf16_kernel(const float* __restrict__ lscale) {
    extern __shared__ uint32_t smu[];
    uint32_t* Kh = smu;
    uint32_t* Kl = smu + OFF_KLO;
    uint32_t* Vh = smu + OFF_VTHI;      // transposed: [d=32][j-word=128]
    uint32_t* Vl = smu + OFF_VTLO;
    float* rn = (float*)(smu + OFF_RN); // q row norms

    const int b = blockIdx.x / NHEAD;
    const int h = blockIdx.x % NHEAD;
    const int tid = threadIdx.x;
    const int lane = tid & 31;
    const int g = lane >> 2, tg = lane & 3;
    const int wm = (tid >> 5) * 32;

    const size_t base = ((size_t)b * NTOK) * CDIM + h * HDIM;
    const float* gq = g_qkv + base;
    const float* gk = g_qkv + (size_t)MROWS * CDIM + base;
    const float* gv = g_qkv + 2ull * MROWS * CDIM + base;
    const float scale2 = __expf(fminf(lscale[h], 4.60517018598809f)) * LOG2E;

    // ---- load phase: thread r handles row r of k, v, q ----
    {
        const int r = tid;
        float tv[32];
        const float* kr = gk + (size_t)r * CDIM;
#pragma unroll
        for (int d = 0; d < HDIM; d += 4) *(float4*)(tv + d) = *(const float4*)(kr + d);
        float ss = 0.f;
#pragma unroll
        for (int d = 0; d < HDIM; d++) ss += tv[d] * tv[d];
        const float rnk = 1.f / fmaxf(sqrtf(ss), 1e-12f);
#pragma unroll
        for (int dw = 0; dw < 16; dw++) {
            uint32_t wh, wl;
            hilo_pack(tv[2 * dw] * rnk, tv[2 * dw + 1] * rnk, wh, wl);
            Kh[r * KSW + dw] = wh;
            Kl[r * KSW + dw] = wl;
        }
        const float* vr = gv + (size_t)r * CDIM;
#pragma unroll
        for (int d = 0; d < HDIM; d += 4) *(float4*)(tv + d) = *(const float4*)(vr + d);
        __nv_bfloat16* Vhb = (__nv_bfloat16*)Vh;
        __nv_bfloat16* Vlb = (__nv_bfloat16*)Vl;
#pragma unroll
        for (int d = 0; d < HDIM; d++) {
            __nv_bfloat16 hi = __float2bfloat16(tv[d]);
            __nv_bfloat16 lo = __float2bfloat16(tv[d] - __bfloat162float(hi));
            Vhb[d * (2 * VSW) + r] = hi;   // word (d, r/2), half r&1
            Vlb[d * (2 * VSW) + r] = lo;
        }
        const float* qr = gq + (size_t)r * CDIM;
#pragma unroll
        for (int d = 0; d < HDIM; d += 4) *(float4*)(tv + d) = *(const float4*)(qr + d);
        ss = 0.f;
#pragma unroll
        for (int d = 0; d < HDIM; d++) ss += tv[d] * tv[d];
        rn[r] = scale2 / fmaxf(sqrtf(ss), 1e-12f);
    }
    __syncthreads();

    // ---- q A-fragments (hi/lo), loaded direct from gmem, kept in regs ----
    uint32_t qh[2][2][4], ql[2][2][4];   // [mtile][kstep][frag]
#pragma unroll
    for (int mt = 0; mt < 2; mt++) {
        const int r0 = wm + mt * 16 + g;
        const float n0 = rn[r0], n1 = rn[r0 + 8];
#pragma unroll
        for (int ks = 0; ks < 2; ks++) {
            const int c0 = 16 * ks + 2 * tg;
            float2 a0 = *(const float2*)(gq + (size_t)r0 * CDIM + c0);
            float2 a1 = *(const float2*)(gq + (size_t)(r0 + 8) * CDIM + c0);
            float2 a2 = *(const float2*)(gq + (size_t)r0 * CDIM + c0 + 8);
            float2 a3 = *(const float2*)(gq + (size_t)(r0 + 8) * CDIM + c0 + 8);
            hilo_pack(a0.x * n0, a0.y * n0, qh[mt][ks][0], ql[mt][ks][0]);
            hilo_pack(a1.x * n1, a1.y * n1, qh[mt][ks][1], ql[mt][ks][1]);
            hilo_pack(a2.x * n0, a2.y * n0, qh[mt][ks][2], ql[mt][ks][2]);
            hilo_pack(a3.x * n1, a3.y * n1, qh[mt][ks][3], ql[mt][ks][3]);
        }
    }

    float oa[2][4][4];
    float lsum[2][2];
#pragma unroll
    for (int mt = 0; mt < 2; mt++) {
        lsum[mt][0] = 0.f; lsum[mt][1] = 0.f;
#pragma unroll
        for (int dt = 0; dt < 4; dt++)
#pragma unroll
            for (int i = 0; i < 4; i++) oa[mt][dt][i] = 0.f;
    }

    const float* rpbh = g_rpb + (size_t)h * NTOK * NTOK;

#pragma unroll 1
    for (int jb = 0; jb < 16; jb++) {
        const int j0 = jb * 16;
        // ---- S = Qn @ Kn^T (3-pass bf16) over 16 j-columns (2 n-tiles) ----
        float sc[2][2][4];
#pragma unroll
        for (int mt = 0; mt < 2; mt++)
#pragma unroll
            for (int nt = 0; nt < 2; nt++)
#pragma unroll
                for (int i = 0; i < 4; i++) sc[mt][nt][i] = 0.f;

        uint32_t kbh[2][2][2], kbl[2][2][2];  // [nt][ks][2]
#pragma unroll
        for (int nt = 0; nt < 2; nt++)
#pragma unroll
            for (int ks = 0; ks < 2; ks++) {
                const uint32_t* kp = Kh + (j0 + nt * 8 + g) * KSW + 8 * ks + tg;
                kbh[nt][ks][0] = kp[0];
                kbh[nt][ks][1] = kp[4];
                const uint32_t* kq = Kl + (j0 + nt * 8 + g) * KSW + 8 * ks + tg;
                kbl[nt][ks][0] = kq[0];
                kbl[nt][ks][1] = kq[4];
            }
#pragma unroll
        for (int mt = 0; mt < 2; mt++)
#pragma unroll
            for (int nt = 0; nt < 2; nt++)
#pragma unroll
                for (int ks = 0; ks < 2; ks++) {
                    mma_bf16(sc[mt][nt], qh[mt][ks], kbh[nt][ks]);
                    mma_bf16(sc[mt][nt], qh[mt][ks], kbl[nt][ks]);
                    mma_bf16(sc[mt][nt], ql[mt][ks], kbh[nt][ks]);
                }

        // ---- + rpb, exp2, l accumulation, pack P hi/lo into A-fragments ----
        uint32_t pha[2][4], pla[2][4];
#pragma unroll
        for (int mt = 0; mt < 2; mt++) {
            const int row = wm + mt * 16 + g;
#pragma unroll
            for (int nt = 0; nt < 2; nt++) {
                const float2 r0 = *(const float2*)(rpbh + (size_t)row * NTOK + j0 + nt * 8 + 2 * tg);
                const float2 r1 = *(const float2*)(rpbh + (size_t)(row + 8) * NTOK + j0 + nt * 8 + 2 * tg);
                const float p0 = ex2(sc[mt][nt][0] + r0.x);
                const float p1 = ex2(sc[mt][nt][1] + r0.y);
                const float p2 = ex2(sc[mt][nt][2] + r1.x);
                const float p3 = ex2(sc[mt][nt][3] + r1.y);
                lsum[mt][0] += p0 + p1;
                lsum[mt][1] += p2 + p3;
                hilo_pack(p0, p1, pha[mt][2 * nt + 0], pla[mt][2 * nt + 0]);
                hilo_pack(p2, p3, pha[mt][2 * nt + 1], pla[mt][2 * nt + 1]);
            }
        }

        // ---- O += P @ V (3-pass bf16), k = this 16-j chunk ----
        uint32_t vbh[4][2], vbl[4][2];
#pragma unroll
        for (int dt = 0; dt < 4; dt++) {
            const uint32_t* vp = Vh + (dt * 8 + g) * VSW + jb * 8 + tg;
            vbh[dt][0] = vp[0];
            vbh[dt][1] = vp[4];
            const uint32_t* vq = Vl + (dt * 8 + g) * VSW + jb * 8 + tg;
            vbl[dt][0] = vq[0];
            vbl[dt][1] = vq[4];
        }
#pragma unroll
        for (int mt = 0; mt < 2; mt++)
#pragma unroll
            for (int dt = 0; dt < 4; dt++) {
                mma_bf16(oa[mt][dt], pha[mt], vbh[dt]);
                mma_bf16(oa[mt][dt], pla[mt], vbh[dt]);
                mma_bf16(oa[mt][dt], pha[mt], vbl[dt]);
            }
    }

    // ---- finalize: row sums across the 4-lane quad, scale, store ----
    float inv[2][2];
#pragma unroll
    for (int mt = 0; mt < 2; mt++)
#pragma unroll
        for (int hh = 0; hh < 2; hh++) {
            float s = lsum[mt][hh];
            s += __shfl_xor_sync(0xffffffffu, s, 1);
            s += __shfl_xor_sync(0xffffffffu, s, 2);
            inv[mt][hh] = 1.f / s;
        }
#pragma unroll
    for (int mt = 0; mt < 2; mt++) {
        const int row = wm + mt * 16 + g;
#pragma unroll
        for (int dt = 0; dt < 4; dt++) {
            const int col = h * HDIM + dt * 8 + 2 * tg;
            float2 o0 = make_float2(oa[mt][dt][0] * inv[mt][0], oa[mt][dt][1] * inv[mt][0]);
            float2 o1 = make_float2(oa[mt][dt][2] * inv[mt][1], oa[mt][dt][3] * inv[mt][1]);
            *(float2*)(g_attout + ((size_t)(b * NTOK + row)) * CDIM + col) = o0;
            *(float2*)(g_attout + ((size_t)(b * NTOK + row + 8)) * CDIM + col) = o1;
        }
    }
}

// ---------------- launch ----------------
extern "C" void kernel_launch(void* const* d_in, const int* in_sizes, int n_in,
                              void* d_out, int out_size) {
    const float* x      = (const float*)d_in[0];
    const float* qkv_w  = (const float*)d_in[1];
    const float* q_bias = (const float*)d_in[2];
    const float* v_bias = (const float*)d_in[3];
    const float* lscale = (const float*)d_in[4];
    const float* cpb_w1 = (const float*)d_in[5];
    const float* cpb_b1 = (const float*)d_in[6];
    const float* cpb_w2 = (const float*)d_in[7];
    const float* proj_w = (const float*)d_in[8];
    const float* proj_b = (const float*)d_in[9];
    const float* table  = (const float*)d_in[10];
    const int*   rpi    = (const int*)d_in[11];
    float* out = (float*)d_out;

    const int attn_smem = ATTN_WORDS * (int)sizeof(uint32_t);  // 75776 B
    cudaFuncSetAttribute(attn_bf16_kernel, cudaFuncAttributeMaxDynamicSharedMemorySize,
                         attn_smem);

    qkv_mma_kernel<<<dim3(9, 512), 256>>>(x, qkv_w, q_bias, v_bias);
    cpb_kernel<<<TBL, 128>>>(table, cpb_w1, cpb_b1, cpb_w2);
    rpb_kernel<<<NHEAD * NTOK, 256>>>(rpi);
    attn_bf16_kernel<<<BWIN * NHEAD, 256, attn_smem>>>(lscale);
    proj_mma_kernel<<<dim3(3, 512), 256>>>(proj_w, proj_b, out);
    (void)in_sizes; (void)n_in; (void)out_size;
}

// round 8
// speedup vs baseline: 2.8218x; 1.0203x over previous
#include <cuda_runtime.h>
#include <cuda_bf16.h>
#include <math.h>
#include <stdint.h>

// Problem constants
#define BWIN 256      // windows*batch
#define NTOK 256      // tokens per window
#define CDIM 384
#define NHEAD 12
#define HDIM 32
#define MROWS (BWIN*NTOK)   // 65536
#define TBL 961             // (2*16-1)^2
#define CPBH 512
#define LOG2E 1.44269504088896f

// ---------------- scratch (device globals; no allocs allowed) ----------------
__device__ float g_qkv[3ull * MROWS * CDIM];     // [3][M][384] f32
__device__ float g_attout[(size_t)MROWS * CDIM]; // [M][384] (tf32-rounded f32)
__device__ float g_xt[(size_t)MROWS * CDIM];     // x pre-rounded to tf32
__device__ float g_wt[3 * CDIM * CDIM];          // qkv_w pre-rounded
__device__ float g_pwt[CDIM * CDIM];             // proj_w pre-rounded
__device__ float g_bt[TBL * NHEAD];
__device__ float g_rpb[(size_t)NHEAD * NTOK * NTOK];

// ---------------- small helpers ----------------
__device__ __forceinline__ uint32_t f2tf(float f) {
    uint32_t u;
    asm("cvt.rna.tf32.f32 %0, %1;" : "=r"(u) : "f"(f));
    return u;
}
__device__ __forceinline__ float ex2(float x) {
    float r;
    asm("ex2.approx.ftz.f32 %0, %1;" : "=f"(r) : "f"(x));
    return r;
}
__device__ __forceinline__ uint32_t smem_u32(const void* p) {
    uint32_t a;
    asm("{ .reg .u64 t; cvta.to.shared.u64 t, %1; cvt.u32.u64 %0, t; }" : "=r"(a) : "l"(p));
    return a;
}
__device__ __forceinline__ void cp16(uint32_t s, const void* g) {
    asm volatile("cp.async.cg.shared.global [%0], [%1], 16;" :: "r"(s), "l"(g) : "memory");
}
__device__ __forceinline__ void mma_tf32(float* c, const uint32_t* a, const uint32_t* b) {
    asm volatile(
        "mma.sync.aligned.m16n8k8.row.col.f32.tf32.tf32.f32 "
        "{%0,%1,%2,%3}, {%4,%5,%6,%7}, {%8,%9}, {%0,%1,%2,%3};\n"
        : "+f"(c[0]), "+f"(c[1]), "+f"(c[2]), "+f"(c[3])
        : "r"(a[0]), "r"(a[1]), "r"(a[2]), "r"(a[3]), "r"(b[0]), "r"(b[1]));
}
__device__ __forceinline__ void mma_bf16(float* c, const uint32_t* a, const uint32_t* b) {
    asm volatile(
        "mma.sync.aligned.m16n8k16.row.col.f32.bf16.bf16.f32 "
        "{%0,%1,%2,%3}, {%4,%5,%6,%7}, {%8,%9}, {%0,%1,%2,%3};\n"
        : "+f"(c[0]), "+f"(c[1]), "+f"(c[2]), "+f"(c[3])
        : "r"(a[0]), "r"(a[1]), "r"(a[2]), "r"(a[3]), "r"(b[0]), "r"(b[1]));
}
__device__ __forceinline__ void hilo_pack(float x, float y, uint32_t& wh, uint32_t& wl) {
    __nv_bfloat16 hx = __float2bfloat16(x);
    __nv_bfloat16 hy = __float2bfloat16(y);
    __nv_bfloat16 lx = __float2bfloat16(x - __bfloat162float(hx));
    __nv_bfloat16 ly = __float2bfloat16(y - __bfloat162float(hy));
    wh = (uint32_t)__bfloat16_as_ushort(hx) | ((uint32_t)__bfloat16_as_ushort(hy) << 16);
    wl = (uint32_t)__bfloat16_as_ushort(lx) | ((uint32_t)__bfloat16_as_ushort(ly) << 16);
}

// ---------------- conversion kernel: round f32 -> tf32 bit pattern ----------------
__global__ __launch_bounds__(256) void cvt_tf32_kernel(const float* __restrict__ in,
                                                       float* __restrict__ out, int n4) {
    int i = blockIdx.x * 256 + threadIdx.x;
    if (i >= n4) return;
    float4 v = ((const float4*)in)[i];
    v.x = __uint_as_float(f2tf(v.x));
    v.y = __uint_as_float(f2tf(v.y));
    v.z = __uint_as_float(f2tf(v.z));
    v.w = __uint_as_float(f2tf(v.w));
    ((float4*)out)[i] = v;
}

// ==================== tf32 mma.sync GEMM, cp.async 5-stage pipeline ====================
// C[m][n] = sum_k A[m][k]*B[n][k], K=384, both operands pre-rounded to tf32 in gmem.
// CTA tile 128x128, 256 thr = 8 warps (2m x 4n), warp tile m64 x n32, K-chunk 16.
// Stage: A/B 128 rows x 16 floats, row stride 20 words (16B-aligned, conflict-free).
#define NSTG 5
#define STW 20
#define STG_A_WORDS (128 * STW)            // 2560 words
#define STG_BYTES (2 * STG_A_WORDS * 4)    // 20480 B (A + B)
#define GEMM_SMEM (NSTG * STG_BYTES)       // 102400 B
#define NCHUNK (CDIM / 16)                 // 24

#define CP_CHUNK(c_) do { \
    const int b_ = (c_) % NSTG; \
    const uint32_t ab_ = sb + b_ * STG_BYTES; \
    const uint32_t bb_ = ab_ + STG_A_WORDS * 4; \
    const float* ga_ = Ag + (size_t)lrow * CDIM + (c_) * 16 + half * 8; \
    const float* gb_ = Bg + (size_t)lrow * CDIM + (c_) * 16 + half * 8; \
    const uint32_t so_ = lrow * (STW * 4) + half * 32; \
    cp16(ab_ + so_, ga_); \
    cp16(ab_ + so_ + 16, ga_ + 4); \
    cp16(bb_ + so_, gb_); \
    cp16(bb_ + so_ + 16, gb_ + 4); \
    asm volatile("cp.async.commit_group;" ::: "memory"); \
} while (0)

__device__ __forceinline__ void mma_gemm_core(
    const float* __restrict__ Ag, const float* __restrict__ Bg,
    float acc[4][4][4], char* smem) {
    const uint32_t sb = smem_u32(smem);
    const int tid = threadIdx.x;
    const int lane = tid & 31;
    const int wm = ((tid >> 5) >> 2) * 64;   // warp m offset (0,64)
    const int wn = ((tid >> 5) & 3) * 32;    // warp n offset (0..96)
    const int g = lane >> 2;                 // 0..7
    const int tg = lane & 3;                 // 0..3
    const int lrow = tid >> 1;               // 0..127
    const int half = tid & 1;                // 0..1

    CP_CHUNK(0); CP_CHUNK(1); CP_CHUNK(2);

#pragma unroll 1
    for (int c = 0; c < NCHUNK; c++) {
        if (c + 3 < NCHUNK) {
            CP_CHUNK(c + 3);
        } else {
            asm volatile("cp.async.commit_group;" ::: "memory");
        }
        asm volatile("cp.async.wait_group 3;" ::: "memory");
        __syncthreads();

        const uint32_t* As = (const uint32_t*)(smem + (c % NSTG) * STG_BYTES);
        const uint32_t* Bs = As + STG_A_WORDS;
#pragma unroll
        for (int ks = 0; ks < 2; ks++) {
            const int kk = ks * 8 + tg;
            uint32_t a[4][4], b[4][2];
#pragma unroll
            for (int mt = 0; mt < 4; mt++) {
                const int row = wm + mt * 16 + g;
                a[mt][0] = As[row * STW + kk];
                a[mt][1] = As[(row + 8) * STW + kk];
                a[mt][2] = As[row * STW + kk + 4];
                a[mt][3] = As[(row + 8) * STW + kk + 4];
            }
#pragma unroll
            for (int nt = 0; nt < 4; nt++) {
                const int col = wn + nt * 8 + g;
                b[nt][0] = Bs[col * STW + kk];
                b[nt][1] = Bs[col * STW + kk + 4];
            }
#pragma unroll
            for (int mt = 0; mt < 4; mt++)
#pragma unroll
                for (int nt = 0; nt < 4; nt++)
                    mma_tf32(acc[mt][nt], a[mt], b[nt]);
        }
    }
}

// QKV: A=g_xt, B=g_wt, out -> g_qkv (+ q/v bias)
__global__ __launch_bounds__(256, 2) void qkv_mma_kernel(
    const float* __restrict__ qb, const float* __restrict__ vb) {
    extern __shared__ char smem[];
    float acc[4][4][4];
#pragma unroll
    for (int i = 0; i < 4; i++)
#pragma unroll
        for (int j = 0; j < 4; j++)
#pragma unroll
            for (int k = 0; k < 4; k++) acc[i][j][k] = 0.f;

    const float* Ag = g_xt + (size_t)blockIdx.y * 128 * CDIM;
    const float* Bg = g_wt + (size_t)blockIdx.x * 128 * CDIM;
    mma_gemm_core(Ag, Bg, acc, smem);

    const int tid = threadIdx.x;
    const int lane = tid & 31;
    const int wm = ((tid >> 5) >> 2) * 64;
    const int wn = ((tid >> 5) & 3) * 32;
    const int g = lane >> 2, tg = lane & 3;

    const int nbase = blockIdx.x * 128;
    const int which = nbase / CDIM;
    const int cb = nbase % CDIM;
    float* outp = g_qkv + (size_t)which * MROWS * CDIM;

#pragma unroll
    for (int mt = 0; mt < 4; mt++) {
        const int row = blockIdx.y * 128 + wm + mt * 16 + g;
#pragma unroll
        for (int nt = 0; nt < 4; nt++) {
            const int col = cb + wn + nt * 8 + 2 * tg;
            float b0 = 0.f, b1 = 0.f;
            if (which == 0) { b0 = qb[col]; b1 = qb[col + 1]; }
            else if (which == 2) { b0 = vb[col]; b1 = vb[col + 1]; }
            float2 o0 = make_float2(acc[mt][nt][0] + b0, acc[mt][nt][1] + b1);
            float2 o1 = make_float2(acc[mt][nt][2] + b0, acc[mt][nt][3] + b1);
            *(float2*)(outp + (size_t)row * CDIM + col) = o0;
            *(float2*)(outp + (size_t)(row + 8) * CDIM + col) = o1;
        }
    }
}

// Proj: A=g_attout (tf32-rounded by attention), B=g_pwt, out -> d_out (+ bias)
__global__ __launch_bounds__(256, 2) void proj_mma_kernel(
    const float* __restrict__ pb, float* __restrict__ out) {
    extern __shared__ char smem[];
    float acc[4][4][4];
#pragma unroll
    for (int i = 0; i < 4; i++)
#pragma unroll
        for (int j = 0; j < 4; j++)
#pragma unroll
            for (int k = 0; k < 4; k++) acc[i][j][k] = 0.f;

    const float* Ag = g_attout + (size_t)blockIdx.y * 128 * CDIM;
    const float* Bg = g_pwt + (size_t)blockIdx.x * 128 * CDIM;
    mma_gemm_core(Ag, Bg, acc, smem);

    const int tid = threadIdx.x;
    const int lane = tid & 31;
    const int wm = ((tid >> 5) >> 2) * 64;
    const int wn = ((tid >> 5) & 3) * 32;
    const int g = lane >> 2, tg = lane & 3;
    const int nbase = blockIdx.x * 128;

#pragma unroll
    for (int mt = 0; mt < 4; mt++) {
        const int row = blockIdx.y * 128 + wm + mt * 16 + g;
#pragma unroll
        for (int nt = 0; nt < 4; nt++) {
            const int col = nbase + wn + nt * 8 + 2 * tg;
            const float b0 = pb[col], b1 = pb[col + 1];
            float2 o0 = make_float2(acc[mt][nt][0] + b0, acc[mt][nt][1] + b1);
            float2 o1 = make_float2(acc[mt][nt][2] + b0, acc[mt][nt][3] + b1);
            *(float2*)(out + (size_t)row * CDIM + col) = o0;
            *(float2*)(out + (size_t)(row + 8) * CDIM + col) = o1;
        }
    }
}

// ---------------- CPB MLP ----------------
__global__ __launch_bounds__(128) void cpb_kernel(
    const float* __restrict__ table, const float* __restrict__ w1,
    const float* __restrict__ b1, const float* __restrict__ w2) {
    __shared__ float hid[CPBH];
    __shared__ float part[NHEAD][9];
    const int r = blockIdx.x;
    const float t0 = table[r * 2 + 0];
    const float t1 = table[r * 2 + 1];
    for (int j = threadIdx.x; j < CPBH; j += 128)
        hid[j] = fmaxf(w1[j * 2] * t0 + w1[j * 2 + 1] * t1 + b1[j], 0.f);
    __syncthreads();
    const int t = threadIdx.x;
    if (t < 96) {
        const int h = t >> 3, seg = t & 7;
        float s = 0.f;
        const float* wr = w2 + h * CPBH + seg * 64;
        const float* hr = hid + seg * 64;
#pragma unroll 8
        for (int j = 0; j < 64; j++) s += hr[j] * wr[j];
        part[h][seg] = s;
    }
    __syncthreads();
    if (t < NHEAD) {
        float s = 0.f;
#pragma unroll
        for (int seg = 0; seg < 8; seg++) s += part[t][seg];
        g_bt[r * NHEAD + t] = s;
    }
}

__global__ __launch_bounds__(256) void rpb_kernel(const int* __restrict__ rpi) {
    const int h = blockIdx.x >> 8;
    const int i = blockIdx.x & 255;
    const int j = threadIdx.x;
    const int idx = rpi[i * NTOK + j];
    const float v = g_bt[idx * NHEAD + h];
    g_rpb[((size_t)(h * NTOK + i)) * NTOK + j] = LOG2E * 16.f / (1.f + __expf(-v));
}

// ============== bf16-split tensor-core attention (P in registers) ==============
#define KSW 20
#define VSW 132
#define OFF_KLO (256*KSW)
#define OFF_VTHI (2*256*KSW)
#define OFF_VTLO (OFF_VTHI + 32*VSW)
#define OFF_RN  (OFF_VTLO + 32*VSW)
#define ATTN_WORDS (OFF_RN + 256)

__global__ __launch_bounds__(256, 2) void attn_bf16_kernel(const float* __restrict__ lscale) {
    extern __shared__ uint32_t smu[];
    uint32_t* Kh = smu;
    uint32_t* Kl = smu + OFF_KLO;
    uint32_t* Vh = smu + OFF_VTHI;
    uint32_t* Vl = smu + OFF_VTLO;
    float* rn = (float*)(smu + OFF_RN);

    const int b = blockIdx.x / NHEAD;
    const int h = blockIdx.x % NHEAD;
    const int tid = threadIdx.x;
    const int lane = tid & 31;
    const int g = lane >> 2, tg = lane & 3;
    const int wm = (tid >> 5) * 32;

    const size_t base = ((size_t)b * NTOK) * CDIM + h * HDIM;
    const float* gq = g_qkv + base;
    const float* gk = g_qkv + (size_t)MROWS * CDIM + base;
    const float* gv = g_qkv + 2ull * MROWS * CDIM + base;
    const float scale2 = __expf(fminf(lscale[h], 4.60517018598809f)) * LOG2E;

    {
        const int r = tid;
        float tv[32];
        const float* kr = gk + (size_t)r * CDIM;
#pragma unroll
        for (int d = 0; d < HDIM; d += 4) *(float4*)(tv + d) = *(const float4*)(kr + d);
        float ss = 0.f;
#pragma unroll
        for (int d = 0; d < HDIM; d++) ss += tv[d] * tv[d];
        const float rnk = 1.f / fmaxf(sqrtf(ss), 1e-12f);
#pragma unroll
        for (int dw = 0; dw < 16; dw++) {
            uint32_t wh, wl;
            hilo_pack(tv[2 * dw] * rnk, tv[2 * dw + 1] * rnk, wh, wl);
            Kh[r * KSW + dw] = wh;
            Kl[r * KSW + dw] = wl;
        }
        const float* vr = gv + (size_t)r * CDIM;
#pragma unroll
        for (int d = 0; d < HDIM; d += 4) *(float4*)(tv + d) = *(const float4*)(vr + d);
        __nv_bfloat16* Vhb = (__nv_bfloat16*)Vh;
        __nv_bfloat16* Vlb = (__nv_bfloat16*)Vl;
#pragma unroll
        for (int d = 0; d < HDIM; d++) {
            __nv_bfloat16 hi = __float2bfloat16(tv[d]);
            __nv_bfloat16 lo = __float2bfloat16(tv[d] - __bfloat162float(hi));
            Vhb[d * (2 * VSW) + r] = hi;
            Vlb[d * (2 * VSW) + r] = lo;
        }
        const float* qr = gq + (size_t)r * CDIM;
#pragma unroll
        for (int d = 0; d < HDIM; d += 4) *(float4*)(tv + d) = *(const float4*)(qr + d);
        ss = 0.f;
#pragma unroll
        for (int d = 0; d < HDIM; d++) ss += tv[d] * tv[d];
        rn[r] = scale2 / fmaxf(sqrtf(ss), 1e-12f);
    }
    __syncthreads();

    uint32_t qh[2][2][4], ql[2][2][4];
#pragma unroll
    for (int mt = 0; mt < 2; mt++) {
        const int r0 = wm + mt * 16 + g;
        const float n0 = rn[r0], n1 = rn[r0 + 8];
#pragma unroll
        for (int ks = 0; ks < 2; ks++) {
            const int c0 = 16 * ks + 2 * tg;
            float2 a0 = *(const float2*)(gq + (size_t)r0 * CDIM + c0);
            float2 a1 = *(const float2*)(gq + (size_t)(r0 + 8) * CDIM + c0);
            float2 a2 = *(const float2*)(gq + (size_t)r0 * CDIM + c0 + 8);
            float2 a3 = *(const float2*)(gq + (size_t)(r0 + 8) * CDIM + c0 + 8);
            hilo_pack(a0.x * n0, a0.y * n0, qh[mt][ks][0], ql[mt][ks][0]);
            hilo_pack(a1.x * n1, a1.y * n1, qh[mt][ks][1], ql[mt][ks][1]);
            hilo_pack(a2.x * n0, a2.y * n0, qh[mt][ks][2], ql[mt][ks][2]);
            hilo_pack(a3.x * n1, a3.y * n1, qh[mt][ks][3], ql[mt][ks][3]);
        }
    }

    float oa[2][4][4];
    float lsum[2][2];
#pragma unroll
    for (int mt = 0; mt < 2; mt++) {
        lsum[mt][0] = 0.f; lsum[mt][1] = 0.f;
#pragma unroll
        for (int dt = 0; dt < 4; dt++)
#pragma unroll
            for (int i = 0; i < 4; i++) oa[mt][dt][i] = 0.f;
    }

    const float* rpbh = g_rpb + (size_t)h * NTOK * NTOK;

#pragma unroll 1
    for (int jb = 0; jb < 16; jb++) {
        const int j0 = jb * 16;
        float sc[2][2][4];
#pragma unroll
        for (int mt = 0; mt < 2; mt++)
#pragma unroll
            for (int nt = 0; nt < 2; nt++)
#pragma unroll
                for (int i = 0; i < 4; i++) sc[mt][nt][i] = 0.f;

        uint32_t kbh[2][2][2], kbl[2][2][2];
#pragma unroll
        for (int nt = 0; nt < 2; nt++)
#pragma unroll
            for (int ks = 0; ks < 2; ks++) {
                const uint32_t* kp = Kh + (j0 + nt * 8 + g) * KSW + 8 * ks + tg;
                kbh[nt][ks][0] = kp[0];
                kbh[nt][ks][1] = kp[4];
                const uint32_t* kq = Kl + (j0 + nt * 8 + g) * KSW + 8 * ks + tg;
                kbl[nt][ks][0] = kq[0];
                kbl[nt][ks][1] = kq[4];
            }
#pragma unroll
        for (int mt = 0; mt < 2; mt++)
#pragma unroll
            for (int nt = 0; nt < 2; nt++)
#pragma unroll
                for (int ks = 0; ks < 2; ks++) {
                    mma_bf16(sc[mt][nt], qh[mt][ks], kbh[nt][ks]);
                    mma_bf16(sc[mt][nt], qh[mt][ks], kbl[nt][ks]);
                    mma_bf16(sc[mt][nt], ql[mt][ks], kbh[nt][ks]);
                }

        uint32_t pha[2][4], pla[2][4];
#pragma unroll
        for (int mt = 0; mt < 2; mt++) {
            const int row = wm + mt * 16 + g;
#pragma unroll
            for (int nt = 0; nt < 2; nt++) {
                const float2 r0 = *(const float2*)(rpbh + (size_t)row * NTOK + j0 + nt * 8 + 2 * tg);
                const float2 r1 = *(const float2*)(rpbh + (size_t)(row + 8) * NTOK + j0 + nt * 8 + 2 * tg);
                const float p0 = ex2(sc[mt][nt][0] + r0.x);
                const float p1 = ex2(sc[mt][nt][1] + r0.y);
                const float p2 = ex2(sc[mt][nt][2] + r1.x);
                const float p3 = ex2(sc[mt][nt][3] + r1.y);
                lsum[mt][0] += p0 + p1;
                lsum[mt][1] += p2 + p3;
                hilo_pack(p0, p1, pha[mt][2 * nt + 0], pla[mt][2 * nt + 0]);
                hilo_pack(p2, p3, pha[mt][2 * nt + 1], pla[mt][2 * nt + 1]);
            }
        }

        uint32_t vbh[4][2], vbl[4][2];
#pragma unroll
        for (int dt = 0; dt < 4; dt++) {
            const uint32_t* vp = Vh + (dt * 8 + g) * VSW + jb * 8 + tg;
            vbh[dt][0] = vp[0];
            vbh[dt][1] = vp[4];
            const uint32_t* vq = Vl + (dt * 8 + g) * VSW + jb * 8 + tg;
            vbl[dt][0] = vq[0];
            vbl[dt][1] = vq[4];
        }
#pragma unroll
        for (int mt = 0; mt < 2; mt++)
#pragma unroll
            for (int dt = 0; dt < 4; dt++) {
                mma_bf16(oa[mt][dt], pha[mt], vbh[dt]);
                mma_bf16(oa[mt][dt], pla[mt], vbh[dt]);
                mma_bf16(oa[mt][dt], pha[mt], vbl[dt]);
            }
    }

    float inv[2][2];
#pragma unroll
    for (int mt = 0; mt < 2; mt++)
#pragma unroll
        for (int hh = 0; hh < 2; hh++) {
            float s = lsum[mt][hh];
            s += __shfl_xor_sync(0xffffffffu, s, 1);
            s += __shfl_xor_sync(0xffffffffu, s, 2);
            inv[mt][hh] = 1.f / s;
        }
    // store tf32-rounded so proj GEMM operand is pre-converted
#pragma unroll
    for (int mt = 0; mt < 2; mt++) {
        const int row = wm + mt * 16 + g;
#pragma unroll
        for (int dt = 0; dt < 4; dt++) {
            const int col = h * HDIM + dt * 8 + 2 * tg;
            float2 o0 = make_float2(__uint_as_float(f2tf(oa[mt][dt][0] * inv[mt][0])),
                                    __uint_as_float(f2tf(oa[mt][dt][1] * inv[mt][0])));
            float2 o1 = make_float2(__uint_as_float(f2tf(oa[mt][dt][2] * inv[mt][1])),
                                    __uint_as_float(f2tf(oa[mt][dt][3] * inv[mt][1])));
            *(float2*)(g_attout + ((size_t)(b * NTOK + row)) * CDIM + col) = o0;
            *(float2*)(g_attout + ((size_t)(b * NTOK + row + 8)) * CDIM + col) = o1;
        }
    }
}

// ---------------- launch ----------------
extern "C" void kernel_launch(void* const* d_in, const int* in_sizes, int n_in,
                              void* d_out, int out_size) {
    const float* x      = (const float*)d_in[0];
    const float* qkv_w  = (const float*)d_in[1];
    const float* q_bias = (const float*)d_in[2];
    const float* v_bias = (const float*)d_in[3];
    const float* lscale = (const float*)d_in[4];
    const float* cpb_w1 = (const float*)d_in[5];
    const float* cpb_b1 = (const float*)d_in[6];
    const float* cpb_w2 = (const float*)d_in[7];
    const float* proj_w = (const float*)d_in[8];
    const float* proj_b = (const float*)d_in[9];
    const float* table  = (const float*)d_in[10];
    const int*   rpi    = (const int*)d_in[11];
    float* out = (float*)d_out;

    const int attn_smem = ATTN_WORDS * (int)sizeof(uint32_t);
    cudaFuncSetAttribute(attn_bf16_kernel, cudaFuncAttributeMaxDynamicSharedMemorySize,
                         attn_smem);
    cudaFuncSetAttribute(qkv_mma_kernel, cudaFuncAttributeMaxDynamicSharedMemorySize,
                         GEMM_SMEM);
    cudaFuncSetAttribute(proj_mma_kernel, cudaFuncAttributeMaxDynamicSharedMemorySize,
                         GEMM_SMEM);

    float *xt_p, *wt_p, *pwt_p;
    cudaGetSymbolAddress((void**)&xt_p, g_xt);
    cudaGetSymbolAddress((void**)&wt_p, g_wt);
    cudaGetSymbolAddress((void**)&pwt_p, g_pwt);

    // pre-round operands to tf32 (hoists all cvt out of GEMM mainloops)
    cvt_tf32_kernel<<<(MROWS * CDIM / 4 + 255) / 256, 256>>>(x, xt_p, MROWS * CDIM / 4);
    cvt_tf32_kernel<<<(3 * CDIM * CDIM / 4 + 255) / 256, 256>>>(qkv_w, wt_p, 3 * CDIM * CDIM / 4);
    cvt_tf32_kernel<<<(CDIM * CDIM / 4 + 255) / 256, 256>>>(proj_w, pwt_p, CDIM * CDIM / 4);

    qkv_mma_kernel<<<dim3(9, 512), 256, GEMM_SMEM>>>(q_bias, v_bias);
    cpb_kernel<<<TBL, 128>>>(table, cpb_w1, cpb_b1, cpb_w2);
    rpb_kernel<<<NHEAD * NTOK, 256>>>(rpi);
    attn_bf16_kernel<<<BWIN * NHEAD, 256, attn_smem>>>(lscale);
    proj_mma_kernel<<<dim3(3, 512), 256, GEMM_SMEM>>>(proj_b, out);
    (void)in_sizes; (void)n_in; (void)out_size;
}

// round 10
// speedup vs baseline: 2.9179x; 1.0341x over previous
#include <cuda_runtime.h>
#include <cuda_bf16.h>
#include <math.h>
#include <stdint.h>

// Problem constants
#define BWIN 256      // windows*batch
#define NTOK 256      // tokens per window
#define CDIM 384
#define NHEAD 12
#define HDIM 32
#define MROWS (BWIN*NTOK)   // 65536
#define TBL 961             // (2*16-1)^2
#define CPBH 512
#define LOG2E 1.44269504088896f

// ---------------- scratch (device globals; no allocs allowed) ----------------
__device__ float g_qkv[3ull * MROWS * CDIM];     // [3][M][384] f32
__device__ float g_attout[(size_t)MROWS * CDIM]; // [M][384] (tf32-rounded f32)
__device__ float g_xt[(size_t)MROWS * CDIM];     // x pre-rounded to tf32
__device__ float g_wt[3 * CDIM * CDIM];          // qkv_w pre-rounded
__device__ float g_pwt[CDIM * CDIM];             // proj_w pre-rounded
__device__ float g_bt[TBL * NHEAD];
__device__ float g_rpb[(size_t)NHEAD * NTOK * NTOK];

// ---------------- small helpers ----------------
__device__ __forceinline__ uint32_t f2tf(float f) {
    uint32_t u;
    asm("cvt.rna.tf32.f32 %0, %1;" : "=r"(u) : "f"(f));
    return u;
}
__device__ __forceinline__ float ex2(float x) {
    float r;
    asm("ex2.approx.ftz.f32 %0, %1;" : "=f"(r) : "f"(x));
    return r;
}
__device__ __forceinline__ uint32_t smem_u32(const void* p) {
    uint32_t a;
    asm("{ .reg .u64 t; cvta.to.shared.u64 t, %1; cvt.u32.u64 %0, t; }" : "=r"(a) : "l"(p));
    return a;
}
__device__ __forceinline__ void cp16(uint32_t s, const void* g) {
    asm volatile("cp.async.cg.shared.global [%0], [%1], 16;" :: "r"(s), "l"(g) : "memory");
}
__device__ __forceinline__ void ldsm_x4(uint32_t& r0, uint32_t& r1, uint32_t& r2,
                                        uint32_t& r3, uint32_t addr) {
    asm volatile("ldmatrix.sync.aligned.m8n8.x4.shared.b16 {%0,%1,%2,%3}, [%4];"
                 : "=r"(r0), "=r"(r1), "=r"(r2), "=r"(r3) : "r"(addr));
}
__device__ __forceinline__ void mma_tf32(float* c, const uint32_t* a, const uint32_t* b) {
    asm volatile(
        "mma.sync.aligned.m16n8k8.row.col.f32.tf32.tf32.f32 "
        "{%0,%1,%2,%3}, {%4,%5,%6,%7}, {%8,%9}, {%0,%1,%2,%3};\n"
        : "+f"(c[0]), "+f"(c[1]), "+f"(c[2]), "+f"(c[3])
        : "r"(a[0]), "r"(a[1]), "r"(a[2]), "r"(a[3]), "r"(b[0]), "r"(b[1]));
}
__device__ __forceinline__ void mma_bf16(float* c, const uint32_t* a, const uint32_t* b) {
    asm volatile(
        "mma.sync.aligned.m16n8k16.row.col.f32.bf16.bf16.f32 "
        "{%0,%1,%2,%3}, {%4,%5,%6,%7}, {%8,%9}, {%0,%1,%2,%3};\n"
        : "+f"(c[0]), "+f"(c[1]), "+f"(c[2]), "+f"(c[3])
        : "r"(a[0]), "r"(a[1]), "r"(a[2]), "r"(a[3]), "r"(b[0]), "r"(b[1]));
}
__device__ __forceinline__ void hilo_pack(float x, float y, uint32_t& wh, uint32_t& wl) {
    __nv_bfloat16 hx = __float2bfloat16(x);
    __nv_bfloat16 hy = __float2bfloat16(y);
    __nv_bfloat16 lx = __float2bfloat16(x - __bfloat162float(hx));
    __nv_bfloat16 ly = __float2bfloat16(y - __bfloat162float(hy));
    wh = (uint32_t)__bfloat16_as_ushort(hx) | ((uint32_t)__bfloat16_as_ushort(hy) << 16);
    wl = (uint32_t)__bfloat16_as_ushort(lx) | ((uint32_t)__bfloat16_as_ushort(ly) << 16);
}

// ---------------- conversion kernel: round f32 -> tf32 bit pattern ----------------
__global__ __launch_bounds__(256) void cvt_tf32_kernel(const float* __restrict__ in,
                                                       float* __restrict__ out, int n4) {
    int i = blockIdx.x * 256 + threadIdx.x;
    if (i >= n4) return;
    float4 v = ((const float4*)in)[i];
    v.x = __uint_as_float(f2tf(v.x));
    v.y = __uint_as_float(f2tf(v.y));
    v.z = __uint_as_float(f2tf(v.z));
    v.w = __uint_as_float(f2tf(v.w));
    ((float4*)out)[i] = v;
}

// ==================== tf32 mma.sync GEMM, cp.async pipeline + ldmatrix ====================
// C[m][n] = sum_k A[m][k]*B[n][k], K=384, operands pre-rounded tf32 in gmem.
// CTA tile 128x128, 256 thr = 8 warps (2m x 4n), warp tile m64 x n32, K-chunk 16.
// Stage rows stride 20 words (80 B): ldmatrix row-set {0,5,2,7,4,1,6,3} mod 8 -> conflict-free.
#define NSTG 5
#define STW 20
#define STG_A_WORDS (128 * STW)            // 2560 words
#define STG_BYTES (2 * STG_A_WORDS * 4)    // 20480 B (A + B)
#define GEMM_SMEM (NSTG * STG_BYTES)       // 102400 B
#define NCHUNK (CDIM / 16)                 // 24

#define CP_CHUNK(c_) do { \
    const int b_ = (c_) % NSTG; \
    const uint32_t ab_ = sb + b_ * STG_BYTES; \
    const uint32_t bb_ = ab_ + STG_A_WORDS * 4; \
    const float* ga_ = Ag + (size_t)lrow * CDIM + (c_) * 16 + half * 8; \
    const float* gb_ = Bg + (size_t)lrow * CDIM + (c_) * 16 + half * 8; \
    const uint32_t so_ = lrow * (STW * 4) + half * 32; \
    cp16(ab_ + so_, ga_); \
    cp16(ab_ + so_ + 16, ga_ + 4); \
    cp16(bb_ + so_, gb_); \
    cp16(bb_ + so_ + 16, gb_ + 4); \
    asm volatile("cp.async.commit_group;" ::: "memory"); \
} while (0)

__device__ __forceinline__ void mma_gemm_core(
    const float* __restrict__ Ag, const float* __restrict__ Bg,
    float acc[4][4][4], char* smem) {
    const uint32_t sb = smem_u32(smem);
    const int tid = threadIdx.x;
    const int lane = tid & 31;
    const int wm = ((tid >> 5) >> 2) * 64;   // warp m offset (0,64)
    const int wn = ((tid >> 5) & 3) * 32;    // warp n offset (0..96)
    const int lrow = tid >> 1;               // 0..127
    const int half = tid & 1;                // 0..1

    // ldmatrix per-lane base offsets (words, within a stage)
    // A x4: m0 rows[0..7]w[0..3], m1 rows[8..15]w[0..3], m2 rows[0..7]w[4..7], m3 rows[8..15]w[4..7]
    const int arow = (lane & 7) + (lane & 8);           // 0..15
    const int acol = (lane & 16) ? 4 : 0;
    const uint32_t aoffw = (uint32_t)((wm + arow) * STW + acol);
    // B x4: m0 cols[nt*8..+7]w[0..3], m1 same cols w[4..7], m2 cols[(nt+1)*8..]w[0..3], m3 w[4..7]
    const int brow = (lane & 7) + ((lane & 16) ? 8 : 0);
    const int bcol = (lane & 8) ? 4 : 0;
    const uint32_t boffw = (uint32_t)((wn + brow) * STW + bcol);

    CP_CHUNK(0); CP_CHUNK(1); CP_CHUNK(2);

#pragma unroll 1
    for (int c = 0; c < NCHUNK; c++) {
        if (c + 3 < NCHUNK) {
            CP_CHUNK(c + 3);
        } else {
            asm volatile("cp.async.commit_group;" ::: "memory");
        }
        asm volatile("cp.async.wait_group 3;" ::: "memory");
        __syncthreads();

        const uint32_t abase = sb + (c % NSTG) * STG_BYTES;
        const uint32_t bbase = abase + STG_A_WORDS * 4;
#pragma unroll
        for (int ks = 0; ks < 2; ks++) {
            uint32_t a[4][4], b[2][4];
#pragma unroll
            for (int mt = 0; mt < 4; mt++)
                ldsm_x4(a[mt][0], a[mt][1], a[mt][2], a[mt][3],
                        abase + ((aoffw + (uint32_t)(mt * 16 * STW + ks * 8)) << 2));
#pragma unroll
            for (int pr = 0; pr < 2; pr++)
                ldsm_x4(b[pr][0], b[pr][1], b[pr][2], b[pr][3],
                        bbase + ((boffw + (uint32_t)(pr * 16 * STW + ks * 8)) << 2));
#pragma unroll
            for (int mt = 0; mt < 4; mt++)
#pragma unroll
                for (int nt = 0; nt < 4; nt++)
                    mma_tf32(acc[mt][nt], a[mt], &b[nt >> 1][(nt & 1) * 2]);
        }
    }
}

// QKV: A=g_xt, B=g_wt, out -> g_qkv (+ q/v bias)
__global__ __launch_bounds__(256, 2) void qkv_mma_kernel(
    const float* __restrict__ qb, const float* __restrict__ vb) {
    extern __shared__ char smem[];
    float acc[4][4][4];
#pragma unroll
    for (int i = 0; i < 4; i++)
#pragma unroll
        for (int j = 0; j < 4; j++)
#pragma unroll
            for (int k = 0; k < 4; k++) acc[i][j][k] = 0.f;

    const float* Ag = g_xt + (size_t)blockIdx.y * 128 * CDIM;
    const float* Bg = g_wt + (size_t)blockIdx.x * 128 * CDIM;
    mma_gemm_core(Ag, Bg, acc, smem);

    const int tid = threadIdx.x;
    const int lane = tid & 31;
    const int wm = ((tid >> 5) >> 2) * 64;
    const int wn = ((tid >> 5) & 3) * 32;
    const int g = lane >> 2, tg = lane & 3;

    const int nbase = blockIdx.x * 128;
    const int which = nbase / CDIM;
    const int cb = nbase % CDIM;
    float* outp = g_qkv + (size_t)which * MROWS * CDIM;

#pragma unroll
    for (int mt = 0; mt < 4; mt++) {
        const int row = blockIdx.y * 128 + wm + mt * 16 + g;
#pragma unroll
        for (int nt = 0; nt < 4; nt++) {
            const int col = cb + wn + nt * 8 + 2 * tg;
            float b0 = 0.f, b1 = 0.f;
            if (which == 0) { b0 = qb[col]; b1 = qb[col + 1]; }
            else if (which == 2) { b0 = vb[col]; b1 = vb[col + 1]; }
            float2 o0 = make_float2(acc[mt][nt][0] + b0, acc[mt][nt][1] + b1);
            float2 o1 = make_float2(acc[mt][nt][2] + b0, acc[mt][nt][3] + b1);
            *(float2*)(outp + (size_t)row * CDIM + col) = o0;
            *(float2*)(outp + (size_t)(row + 8) * CDIM + col) = o1;
        }
    }
}

// Proj: A=g_attout (tf32-rounded by attention), B=g_pwt, out -> d_out (+ bias)
__global__ __launch_bounds__(256, 2) void proj_mma_kernel(
    const float* __restrict__ pb, float* __restrict__ out) {
    extern __shared__ char smem[];
    float acc[4][4][4];
#pragma unroll
    for (int i = 0; i < 4; i++)
#pragma unroll
        for (int j = 0; j < 4; j++)
#pragma unroll
            for (int k = 0; k < 4; k++) acc[i][j][k] = 0.f;

    const float* Ag = g_attout + (size_t)blockIdx.y * 128 * CDIM;
    const float* Bg = g_pwt + (size_t)blockIdx.x * 128 * CDIM;
    mma_gemm_core(Ag, Bg, acc, smem);

    const int tid = threadIdx.x;
    const int lane = tid & 31;
    const int wm = ((tid >> 5) >> 2) * 64;
    const int wn = ((tid >> 5) & 3) * 32;
    const int g = lane >> 2, tg = lane & 3;
    const int nbase = blockIdx.x * 128;

#pragma unroll
    for (int mt = 0; mt < 4; mt++) {
        const int row = blockIdx.y * 128 + wm + mt * 16 + g;
#pragma unroll
        for (int nt = 0; nt < 4; nt++) {
            const int col = nbase + wn + nt * 8 + 2 * tg;
            const float b0 = pb[col], b1 = pb[col + 1];
            float2 o0 = make_float2(acc[mt][nt][0] + b0, acc[mt][nt][1] + b1);
            float2 o1 = make_float2(acc[mt][nt][2] + b0, acc[mt][nt][3] + b1);
            *(float2*)(out + (size_t)row * CDIM + col) = o0;
            *(float2*)(out + (size_t)(row + 8) * CDIM + col) = o1;
        }
    }
}

// ---------------- CPB MLP ----------------
__global__ __launch_bounds__(128) void cpb_kernel(
    const float* __restrict__ table, const float* __restrict__ w1,
    const float* __restrict__ b1, const float* __restrict__ w2) {
    __shared__ float hid[CPBH];
    __shared__ float part[NHEAD][9];
    const int r = blockIdx.x;
    const float t0 = table[r * 2 + 0];
    const float t1 = table[r * 2 + 1];
    for (int j = threadIdx.x; j < CPBH; j += 128)
        hid[j] = fmaxf(w1[j * 2] * t0 + w1[j * 2 + 1] * t1 + b1[j], 0.f);
    __syncthreads();
    const int t = threadIdx.x;
    if (t < 96) {
        const int h = t >> 3, seg = t & 7;
        float s = 0.f;
        const float* wr = w2 + h * CPBH + seg * 64;
        const float* hr = hid + seg * 64;
#pragma unroll 8
        for (int j = 0; j < 64; j++) s += hr[j] * wr[j];
        part[h][seg] = s;
    }
    __syncthreads();
    if (t < NHEAD) {
        float s = 0.f;
#pragma unroll
        for (int seg = 0; seg < 8; seg++) s += part[t][seg];
        g_bt[r * NHEAD + t] = s;
    }
}

__global__ __launch_bounds__(256) void rpb_kernel(const int* __restrict__ rpi) {
    const int h = blockIdx.x >> 8;
    const int i = blockIdx.x & 255;
    const int j = threadIdx.x;
    const int idx = rpi[i * NTOK + j];
    const float v = g_bt[idx * NHEAD + h];
    g_rpb[((size_t)(h * NTOK + i)) * NTOK + j] = LOG2E * 16.f / (1.f + __expf(-v));
}

// ============== bf16-split tensor-core attention (P in registers) ==============
#define KSW 20
#define VSW 132
#define OFF_KLO (256*KSW)
#define OFF_VTHI (2*256*KSW)
#define OFF_VTLO (OFF_VTHI + 32*VSW)
#define OFF_RN  (OFF_VTLO + 32*VSW)
#define ATTN_WORDS (OFF_RN + 256)

__global__ __launch_bounds__(256, 2) void attn_bf16_kernel(const float* __restrict__ lscale) {
    extern __shared__ uint32_t smu[];
    uint32_t* Kh = smu;
    uint32_t* Kl = smu + OFF_KLO;
    uint32_t* Vh = smu + OFF_VTHI;
    uint32_t* Vl = smu + OFF_VTLO;
    float* rn = (float*)(smu + OFF_RN);

    const int b = blockIdx.x / NHEAD;
    const int h = blockIdx.x % NHEAD;
    const int tid = threadIdx.x;
    const int lane = tid & 31;
    const int g = lane >> 2, tg = lane & 3;
    const int wm = (tid >> 5) * 32;

    const size_t base = ((size_t)b * NTOK) * CDIM + h * HDIM;
    const float* gq = g_qkv + base;
    const float* gk = g_qkv + (size_t)MROWS * CDIM + base;
    const float* gv = g_qkv + 2ull * MROWS * CDIM + base;
    const float scale2 = __expf(fminf(lscale[h], 4.60517018598809f)) * LOG2E;

    {
        const int r = tid;
        float tv[32];
        const float* kr = gk + (size_t)r * CDIM;
#pragma unroll
        for (int d = 0; d < HDIM; d += 4) *(float4*)(tv + d) = *(const float4*)(kr + d);
        float ss = 0.f;
#pragma unroll
        for (int d = 0; d < HDIM; d++) ss += tv[d] * tv[d];
        const float rnk = 1.f / fmaxf(sqrtf(ss), 1e-12f);
#pragma unroll
        for (int dw = 0; dw < 16; dw++) {
            uint32_t wh, wl;
            hilo_pack(tv[2 * dw] * rnk, tv[2 * dw + 1] * rnk, wh, wl);
            Kh[r * KSW + dw] = wh;
            Kl[r * KSW + dw] = wl;
        }
        const float* vr = gv + (size_t)r * CDIM;
#pragma unroll
        for (int d = 0; d < HDIM; d += 4) *(float4*)(tv + d) = *(const float4*)(vr + d);
        __nv_bfloat16* Vhb = (__nv_bfloat16*)Vh;
        __nv_bfloat16* Vlb = (__nv_bfloat16*)Vl;
#pragma unroll
        for (int d = 0; d < HDIM; d++) {
            __nv_bfloat16 hi = __float2bfloat16(tv[d]);
            __nv_bfloat16 lo = __float2bfloat16(tv[d] - __bfloat162float(hi));
            Vhb[d * (2 * VSW) + r] = hi;
            Vlb[d * (2 * VSW) + r] = lo;
        }
        const float* qr = gq + (size_t)r * CDIM;
#pragma unroll
        for (int d = 0; d < HDIM; d += 4) *(float4*)(tv + d) = *(const float4*)(qr + d);
        ss = 0.f;
#pragma unroll
        for (int d = 0; d < HDIM; d++) ss += tv[d] * tv[d];
        rn[r] = scale2 / fmaxf(sqrtf(ss), 1e-12f);
    }
    __syncthreads();

    uint32_t qh[2][2][4], ql[2][2][4];
#pragma unroll
    for (int mt = 0; mt < 2; mt++) {
        const int r0 = wm + mt * 16 + g;
        const float n0 = rn[r0], n1 = rn[r0 + 8];
#pragma unroll
        for (int ks = 0; ks < 2; ks++) {
            const int c0 = 16 * ks + 2 * tg;
            float2 a0 = *(const float2*)(gq + (size_t)r0 * CDIM + c0);
            float2 a1 = *(const float2*)(gq + (size_t)(r0 + 8) * CDIM + c0);
            float2 a2 = *(const float2*)(gq + (size_t)r0 * CDIM + c0 + 8);
            float2 a3 = *(const float2*)(gq + (size_t)(r0 + 8) * CDIM + c0 + 8);
            hilo_pack(a0.x * n0, a0.y * n0, qh[mt][ks][0], ql[mt][ks][0]);
            hilo_pack(a1.x * n1, a1.y * n1, qh[mt][ks][1], ql[mt][ks][1]);
            hilo_pack(a2.x * n0, a2.y * n0, qh[mt][ks][2], ql[mt][ks][2]);
            hilo_pack(a3.x * n1, a3.y * n1, qh[mt][ks][3], ql[mt][ks][3]);
        }
    }

    float oa[2][4][4];
    float lsum[2][2];
#pragma unroll
    for (int mt = 0; mt < 2; mt++) {
        lsum[mt][0] = 0.f; lsum[mt][1] = 0.f;
#pragma unroll
        for (int dt = 0; dt < 4; dt++)
#pragma unroll
            for (int i = 0; i < 4; i++) oa[mt][dt][i] = 0.f;
    }

    const float* rpbh = g_rpb + (size_t)h * NTOK * NTOK;

#pragma unroll 1
    for (int jb = 0; jb < 16; jb++) {
        const int j0 = jb * 16;
        float sc[2][2][4];
#pragma unroll
        for (int mt = 0; mt < 2; mt++)
#pragma unroll
            for (int nt = 0; nt < 2; nt++)
#pragma unroll
                for (int i = 0; i < 4; i++) sc[mt][nt][i] = 0.f;

        uint32_t kbh[2][2][2], kbl[2][2][2];
#pragma unroll
        for (int nt = 0; nt < 2; nt++)
#pragma unroll
            for (int ks = 0; ks < 2; ks++) {
                const uint32_t* kp = Kh + (j0 + nt * 8 + g) * KSW + 8 * ks + tg;
                kbh[nt][ks][0] = kp[0];
                kbh[nt][ks][1] = kp[4];
                const uint32_t* kq = Kl + (j0 + nt * 8 + g) * KSW + 8 * ks + tg;
                kbl[nt][ks][0] = kq[0];
                kbl[nt][ks][1] = kq[4];
            }
#pragma unroll
        for (int mt = 0; mt < 2; mt++)
#pragma unroll
            for (int nt = 0; nt < 2; nt++)
#pragma unroll
                for (int ks = 0; ks < 2; ks++) {
                    mma_bf16(sc[mt][nt], qh[mt][ks], kbh[nt][ks]);
                    mma_bf16(sc[mt][nt], qh[mt][ks], kbl[nt][ks]);
                    mma_bf16(sc[mt][nt], ql[mt][ks], kbh[nt][ks]);
                }

        uint32_t pha[2][4], pla[2][4];
#pragma unroll
        for (int mt = 0; mt < 2; mt++) {
            const int row = wm + mt * 16 + g;
#pragma unroll
            for (int nt = 0; nt < 2; nt++) {
                const float2 r0 = *(const float2*)(rpbh + (size_t)row * NTOK + j0 + nt * 8 + 2 * tg);
                const float2 r1 = *(const float2*)(rpbh + (size_t)(row + 8) * NTOK + j0 + nt * 8 + 2 * tg);
                const float p0 = ex2(sc[mt][nt][0] + r0.x);
                const float p1 = ex2(sc[mt][nt][1] + r0.y);
                const float p2 = ex2(sc[mt][nt][2] + r1.x);
                const float p3 = ex2(sc[mt][nt][3] + r1.y);
                lsum[mt][0] += p0 + p1;
                lsum[mt][1] += p2 + p3;
                hilo_pack(p0, p1, pha[mt][2 * nt + 0], pla[mt][2 * nt + 0]);
                hilo_pack(p2, p3, pha[mt][2 * nt + 1], pla[mt][2 * nt + 1]);
            }
        }

        uint32_t vbh[4][2], vbl[4][2];
#pragma unroll
        for (int dt = 0; dt < 4; dt++) {
            const uint32_t* vp = Vh + (dt * 8 + g) * VSW + jb * 8 + tg;
            vbh[dt][0] = vp[0];
            vbh[dt][1] = vp[4];
            const uint32_t* vq = Vl + (dt * 8 + g) * VSW + jb * 8 + tg;
            vbl[dt][0] = vq[0];
            vbl[dt][1] = vq[4];
        }
#pragma unroll
        for (int mt = 0; mt < 2; mt++)
#pragma unroll
            for (int dt = 0; dt < 4; dt++) {
                mma_bf16(oa[mt][dt], pha[mt], vbh[dt]);
                mma_bf16(oa[mt][dt], pla[mt], vbh[dt]);
                mma_bf16(oa[mt][dt], pha[mt], vbl[dt]);
            }
    }

    float inv[2][2];
#pragma unroll
    for (int mt = 0; mt < 2; mt++)
#pragma unroll
        for (int hh = 0; hh < 2; hh++) {
            float s = lsum[mt][hh];
            s += __shfl_xor_sync(0xffffffffu, s, 1);
            s += __shfl_xor_sync(0xffffffffu, s, 2);
            inv[mt][hh] = 1.f / s;
        }
    // store tf32-rounded so proj GEMM operand is pre-converted
#pragma unroll
    for (int mt = 0; mt < 2; mt++) {
        const int row = wm + mt * 16 + g;
#pragma unroll
        for (int dt = 0; dt < 4; dt++) {
            const int col = h * HDIM + dt * 8 + 2 * tg;
            float2 o0 = make_float2(__uint_as_float(f2tf(oa[mt][dt][0] * inv[mt][0])),
                                    __uint_as_float(f2tf(oa[mt][dt][1] * inv[mt][0])));
            float2 o1 = make_float2(__uint_as_float(f2tf(oa[mt][dt][2] * inv[mt][1])),
                                    __uint_as_float(f2tf(oa[mt][dt][3] * inv[mt][1])));
            *(float2*)(g_attout + ((size_t)(b * NTOK + row)) * CDIM + col) = o0;
            *(float2*)(g_attout + ((size_t)(b * NTOK + row + 8)) * CDIM + col) = o1;
        }
    }
}

// ---------------- launch ----------------
extern "C" void kernel_launch(void* const* d_in, const int* in_sizes, int n_in,
                              void* d_out, int out_size) {
    const float* x      = (const float*)d_in[0];
    const float* qkv_w  = (const float*)d_in[1];
    const float* q_bias = (const float*)d_in[2];
    const float* v_bias = (const float*)d_in[3];
    const float* lscale = (const float*)d_in[4];
    const float* cpb_w1 = (const float*)d_in[5];
    const float* cpb_b1 = (const float*)d_in[6];
    const float* cpb_w2 = (const float*)d_in[7];
    const float* proj_w = (const float*)d_in[8];
    const float* proj_b = (const float*)d_in[9];
    const float* table  = (const float*)d_in[10];
    const int*   rpi    = (const int*)d_in[11];
    float* out = (float*)d_out;

    const int attn_smem = ATTN_WORDS * (int)sizeof(uint32_t);
    cudaFuncSetAttribute(attn_bf16_kernel, cudaFuncAttributeMaxDynamicSharedMemorySize,
                         attn_smem);
    cudaFuncSetAttribute(qkv_mma_kernel, cudaFuncAttributeMaxDynamicSharedMemorySize,
                         GEMM_SMEM);
    cudaFuncSetAttribute(proj_mma_kernel, cudaFuncAttributeMaxDynamicSharedMemorySize,
                         GEMM_SMEM);

    float *xt_p, *wt_p, *pwt_p;
    cudaGetSymbolAddress((void**)&xt_p, g_xt);
    cudaGetSymbolAddress((void**)&wt_p, g_wt);
    cudaGetSymbolAddress((void**)&pwt_p, g_pwt);

    // pre-round operands to tf32 (hoists all cvt out of GEMM mainloops)
    cvt_tf32_kernel<<<(MROWS * CDIM / 4 + 255) / 256, 256>>>(x, xt_p, MROWS * CDIM / 4);
    cvt_tf32_kernel<<<(3 * CDIM * CDIM / 4 + 255) / 256, 256>>>(qkv_w, wt_p, 3 * CDIM * CDIM / 4);
    cvt_tf32_kernel<<<(CDIM * CDIM / 4 + 255) / 256, 256>>>(proj_w, pwt_p, CDIM * CDIM / 4);

    qkv_mma_kernel<<<dim3(9, 512), 256, GEMM_SMEM>>>(q_bias, v_bias);
    cpb_kernel<<<TBL, 128>>>(table, cpb_w1, cpb_b1, cpb_w2);
    rpb_kernel<<<NHEAD * NTOK, 256>>>(rpi);
    attn_bf16_kernel<<<BWIN * NHEAD, 256, attn_smem>>>(lscale);
    proj_mma_kernel<<<dim3(3, 512), 256, GEMM_SMEM>>>(proj_b, out);
    (void)in_sizes; (void)n_in; (void)out_size;
}